// round 6
// baseline (speedup 1.0000x reference)
#include <cuda_runtime.h>
#include <cuda_bf16.h>
#include <cstdint>

#define HID 1024
#define MROWS 32768
#define STAGE 40960
#define NSTAGE 4
#define DSMEM_TOTAL (NSTAGE * STAGE)

// ---- static device scratch (allocation-free rule) ----
__device__ __align__(16) __nv_bfloat16 g_x_hi [(size_t)MROWS * 512];
__device__ __align__(16) __nv_bfloat16 g_x_lo [(size_t)MROWS * 512];
__device__ __align__(16) __nv_bfloat16 g_w_hi [(size_t)3 * HID * 512];
__device__ __align__(16) __nv_bfloat16 g_w_lo [(size_t)3 * HID * 512];
__device__ __align__(16) __nv_bfloat16 g_WH_hi[(size_t)5 * HID * HID];
__device__ __align__(16) __nv_bfloat16 g_WH_lo[(size_t)5 * HID * HID];
__device__ __align__(16) __nv_bfloat16 g_WT_hi[(size_t)5 * HID * HID];
__device__ __align__(16) __nv_bfloat16 g_WT_lo[(size_t)5 * HID * HID];
__device__ __align__(16) __nv_bfloat16 g_WC_hi[(size_t)5 * HID * HID];
__device__ __align__(16) __nv_bfloat16 g_WC_lo[(size_t)5 * HID * HID];
__device__ __align__(16) __nv_bfloat16 g_hA_hi[(size_t)MROWS * HID];
__device__ __align__(16) __nv_bfloat16 g_hA_lo[(size_t)MROWS * HID];
__device__ __align__(16) __nv_bfloat16 g_hB_hi[(size_t)MROWS * HID];
__device__ __align__(16) __nv_bfloat16 g_hB_lo[(size_t)MROWS * HID];

// ---- helpers ----
__device__ __forceinline__ uint32_t smem_u32(const void* p) {
    uint32_t a;
    asm("{ .reg .u64 t; cvta.to.shared.u64 t, %1; cvt.u32.u64 %0, t; }" : "=r"(a) : "l"(p));
    return a;
}
__device__ __forceinline__ void cpa16(uint32_t s, const void* g) {
    asm volatile("cp.async.cg.shared.global [%0], [%1], 16;" :: "r"(s), "l"(g));
}
__device__ __forceinline__ void cpa_commit() {
    asm volatile("cp.async.commit_group;" ::: "memory");
}
__device__ __forceinline__ void cpa_wait2() {
    asm volatile("cp.async.wait_group 2;" ::: "memory");
}
__device__ __forceinline__ void ldsm4(uint32_t* r, uint32_t a) {
    asm volatile("ldmatrix.sync.aligned.m8n8.x4.shared.b16 {%0,%1,%2,%3}, [%4];"
                 : "=r"(r[0]), "=r"(r[1]), "=r"(r[2]), "=r"(r[3]) : "r"(a));
}
__device__ __forceinline__ void mma16816(float* d, const uint32_t* a, uint32_t b0, uint32_t b1) {
    asm volatile(
        "mma.sync.aligned.m16n8k16.row.col.f32.bf16.bf16.f32 "
        "{%0,%1,%2,%3}, {%4,%5,%6,%7}, {%8,%9}, {%0,%1,%2,%3};"
        : "+f"(d[0]), "+f"(d[1]), "+f"(d[2]), "+f"(d[3])
        : "r"(a[0]), "r"(a[1]), "r"(a[2]), "r"(a[3]), "r"(b0), "r"(b1));
}
// swizzled byte offset of 16B chunk (row r, chunk c in 0..3) of a k32-wide tile
__device__ __forceinline__ uint32_t swz(int r, int c) {
    return (uint32_t)((r >> 1) * 128 + (r & 1) * 64 + ((c ^ ((r >> 1) & 3)) << 4));
}
__device__ __forceinline__ float sigm_(float x) { return __fdividef(1.f, 1.f + __expf(-x)); }
__device__ __forceinline__ float tanh_(float x) {
    float ax = fabsf(x), e = __expf(-2.f * ax);
    float t = __fdividef(1.f - e, 1.f + e);
    return x >= 0.f ? t : -t;
}
__device__ __forceinline__ float bf2f(uint32_t b) { return __uint_as_float(b << 16); }
__device__ __forceinline__ uint32_t f2bf(float f) {
    return (uint32_t)__bfloat16_as_ushort(__float2bfloat16(f));
}

// ---- split fp32 -> (hi, lo) bf16 ----
__global__ void split4(const float4* __restrict__ src, uint2* __restrict__ hi,
                       uint2* __restrict__ lo, int n4) {
    int i = blockIdx.x * blockDim.x + threadIdx.x;
    if (i >= n4) return;
    float4 v = src[i];
    float vv[4] = {v.x, v.y, v.z, v.w};
    uint32_t h[4], l[4];
#pragma unroll
    for (int k = 0; k < 4; k++) {
        h[k] = f2bf(vv[k]);
        l[k] = f2bf(vv[k] - bf2f(h[k]));
    }
    hi[i] = make_uint2(h[0] | (h[1] << 16), h[2] | (h[3] << 16));
    lo[i] = make_uint2(l[0] | (l[1] << 16), l[2] | (l[3] << 16));
}

__global__ void split4w(const float4* __restrict__ s0, uint2* __restrict__ h0, uint2* __restrict__ l0,
                        const float4* __restrict__ s1, uint2* __restrict__ h1, uint2* __restrict__ l1,
                        const float4* __restrict__ s2, uint2* __restrict__ h2, uint2* __restrict__ l2,
                        int n4) {
    int i = blockIdx.x * blockDim.x + threadIdx.x;
    if (i >= n4) return;
    const float4* src = blockIdx.z == 0 ? s0 : (blockIdx.z == 1 ? s1 : s2);
    uint2* hi = blockIdx.z == 0 ? h0 : (blockIdx.z == 1 ? h1 : h2);
    uint2* lo = blockIdx.z == 0 ? l0 : (blockIdx.z == 1 ? l1 : l2);
    float4 v = src[i];
    float vv[4] = {v.x, v.y, v.z, v.w};
    uint32_t h[4], l[4];
#pragma unroll
    for (int k = 0; k < 4; k++) {
        h[k] = f2bf(vv[k]);
        l[k] = f2bf(vv[k] - bf2f(h[k]));
    }
    hi[i] = make_uint2(h[0] | (h[1] << 16), h[2] | (h[3] << 16));
    lo[i] = make_uint2(l[0] | (l[1] << 16), l[2] | (l[3] << 16));
}

// ---- fused 3-gate mma.sync GEMM + epilogue ----
// CTA tile: M=128, N=64 per gate, 3 gates. 256 threads, 8 warps: wm=wid&1 (64 rows),
// wn=wid>>1 (16 cols). smem stage: Ahi[0,8K) Alo[8K,16K) B[16K+(g*2+t)*4K).
template<int KF, int MODE, int WSPLIT>
__global__ void __launch_bounds__(256, 1)
rhn_mma(const __nv_bfloat16* __restrict__ Ahi, const __nv_bfloat16* __restrict__ Alo,
        const __nv_bfloat16* __restrict__ B0hi, const __nv_bfloat16* __restrict__ B0lo,
        const __nv_bfloat16* __restrict__ B1hi, const __nv_bfloat16* __restrict__ B1lo,
        const __nv_bfloat16* __restrict__ B2hi, const __nv_bfloat16* __restrict__ B2lo,
        const float* __restrict__ e0, const float* __restrict__ e1, const float* __restrict__ e2,
        const __nv_bfloat16* __restrict__ hinHi, const __nv_bfloat16* __restrict__ hinLo,
        float* __restrict__ outF,
        __nv_bfloat16* __restrict__ outHi, __nv_bfloat16* __restrict__ outLo)
{
    constexpr int NK = KF / 32;
    extern __shared__ __align__(128) uint8_t smemraw[];
    const uint32_t sbase = smem_u32(smemraw);

    const int tid = threadIdx.x;
    const int lane = tid & 31;
    const int wm = (tid >> 5) & 1;
    const int wn = tid >> 6;
    const int m0 = blockIdx.y * 128;
    const int n0 = blockIdx.x * 64;

    // ---- producer: 10 x 16B cp.async per thread per stage, bumped pointers ----
    const char* cp[10];
    uint32_t so[10];
    {
        const int pr = tid >> 2;
        const int pc = tid & 3;
        cp[0] = (const char*)(Ahi + (size_t)(m0 + pr) * KF + pc * 8);
        cp[1] = (const char*)(Ahi + (size_t)(m0 + pr + 64) * KF + pc * 8);
        cp[2] = (const char*)(Alo + (size_t)(m0 + pr) * KF + pc * 8);
        cp[3] = (const char*)(Alo + (size_t)(m0 + pr + 64) * KF + pc * 8);
        so[0] = swz(pr, pc);
        so[1] = swz(pr + 64, pc);
        so[2] = 8192u + swz(pr, pc);
        so[3] = 8192u + swz(pr + 64, pc);
        const __nv_bfloat16* bp[6] = {B0hi, B0lo, B1hi, B1lo, B2hi, B2lo};
#pragma unroll
        for (int t = 0; t < 6; t++) {
            cp[4 + t] = (const char*)(bp[t] + (size_t)(n0 + pr) * KF + pc * 8);
            so[4 + t] = 16384u + t * 4096u + swz(pr, pc);
        }
    }

    // ---- consumer: precompute ALL ldmatrix offsets (chunk-invariant) ----
    const int mat = lane >> 3;
    const int khf = lane >> 4;
    uint32_t aoff[4][2];   // [mi][ks], hi tile; lo = +8192
    uint32_t boff[2];      // [ks], base of B block; per (g,t) add 16384+(g*2+t)*4096
#pragma unroll
    for (int mi = 0; mi < 4; mi++) {
        int r = wm * 64 + mi * 16 + (mat & 1) * 8 + (lane & 7);
        uint32_t base = (uint32_t)((r >> 1) * 128 + (r & 1) * 64);
        int sw = (r >> 1) & 3;
#pragma unroll
        for (int ks = 0; ks < 2; ks++)
            aoff[mi][ks] = base + (uint32_t)(((ks * 2 + khf) ^ sw) << 4);
    }
    {
        int r = wn * 16 + (mat & 1) * 8 + (lane & 7);
        uint32_t base = (uint32_t)((r >> 1) * 128 + (r & 1) * 64);
        int sw = (r >> 1) & 3;
#pragma unroll
        for (int ks = 0; ks < 2; ks++)
            boff[ks] = base + (uint32_t)(((ks * 2 + khf) ^ sw) << 4);
    }

    float acc[3][4][2][4];
#pragma unroll
    for (int g = 0; g < 3; g++)
#pragma unroll
        for (int mi = 0; mi < 4; mi++)
#pragma unroll
            for (int nf = 0; nf < 2; nf++)
#pragma unroll
                for (int e = 0; e < 4; e++) acc[g][mi][nf][e] = 0.f;

    // preload stages 0..2
#pragma unroll
    for (int s = 0; s < 3; s++) {
        uint32_t sb_ = sbase + s * STAGE;
#pragma unroll
        for (int j = 0; j < 10; j++) cpa16(sb_ + so[j], cp[j] + (size_t)s * 64);
        cpa_commit();
    }
#pragma unroll
    for (int j = 0; j < 10; j++) cp[j] += 192;   // now at chunk 3

    uint32_t rd = sbase;
    uint32_t wr = sbase + 3u * STAGE;
    const uint32_t send = sbase + 4u * STAGE;

    for (int i = 0; i < NK; i++) {
        cpa_wait2();
        __syncthreads();

        // issue chunk i+3 into slot (i+3)&3 (overwrites stage i-1, drained above)
        if (i + 3 < NK) {
#pragma unroll
            for (int j = 0; j < 10; j++) { cpa16(wr + so[j], cp[j]); cp[j] += 64; }
        }
        cpa_commit();

#pragma unroll
        for (int ks = 0; ks < 2; ks++) {
            uint32_t aH[16], aL[16];
#pragma unroll
            for (int mi = 0; mi < 4; mi++) {
                uint32_t ad = rd + aoff[mi][ks];
                ldsm4(&aH[mi * 4], ad);
                ldsm4(&aL[mi * 4], ad + 8192u);
            }
            const uint32_t bb = rd + boff[ks] + 16384u;
#pragma unroll
            for (int g = 0; g < 3; g++) {
                uint32_t bh[4], bl[4];
                ldsm4(bh, bb + (g * 2 + 0) * 4096u);
                ldsm4(bl, bb + (g * 2 + 1) * 4096u);
#pragma unroll
                for (int mi = 0; mi < 4; mi++) {
                    mma16816(acc[g][mi][0], &aH[mi * 4], bh[0], bh[2]);
                    mma16816(acc[g][mi][1], &aH[mi * 4], bh[1], bh[3]);
                    mma16816(acc[g][mi][0], &aH[mi * 4], bl[0], bl[2]);
                    mma16816(acc[g][mi][1], &aH[mi * 4], bl[1], bl[3]);
                    mma16816(acc[g][mi][0], &aL[mi * 4], bh[0], bh[2]);
                    mma16816(acc[g][mi][1], &aL[mi * 4], bh[1], bh[3]);
                }
            }
        }
        rd += STAGE; if (rd == send) rd = sbase;
        wr += STAGE; if (wr == send) wr = sbase;
    }

    // ---- epilogue ----
    float bA[2][2], bB[2][2], bC2[2][2], bD[2][2];
#pragma unroll
    for (int nf = 0; nf < 2; nf++) {
        int n = n0 + wn * 16 + nf * 8 + (lane & 3) * 2;
        if (MODE == 0) {
            float2 i0 = *(const float2*)&e0[n],         h0 = *(const float2*)&e1[n];
            float2 i1 = *(const float2*)&e0[HID + n],   h1 = *(const float2*)&e1[HID + n];
            float2 i2 = *(const float2*)&e0[2*HID + n], h2 = *(const float2*)&e1[2*HID + n];
            bA[nf][0] = i0.x + h0.x; bA[nf][1] = i0.y + h0.y;
            bB[nf][0] = i1.x + h1.x; bB[nf][1] = i1.y + h1.y;
            bC2[nf][0] = i2.x;       bC2[nf][1] = i2.y;
            bD[nf][0] = h2.x;        bD[nf][1] = h2.y;
        } else {
            float2 v0 = *(const float2*)&e0[n];
            float2 v1 = *(const float2*)&e1[n];
            float2 v2 = *(const float2*)&e2[n];
            bA[nf][0] = v0.x; bA[nf][1] = v0.y;
            bB[nf][0] = v1.x; bB[nf][1] = v1.y;
            bC2[nf][0] = v2.x; bC2[nf][1] = v2.y;
        }
    }

#pragma unroll
    for (int mi = 0; mi < 4; mi++) {
#pragma unroll
        for (int half = 0; half < 2; half++) {
            const int m = m0 + wm * 64 + mi * 16 + (lane >> 2) + half * 8;
#pragma unroll
            for (int nf = 0; nf < 2; nf++) {
                const int n = n0 + wn * 16 + nf * 8 + (lane & 3) * 2;
                float res[2];
#pragma unroll
                for (int e = 0; e < 2; e++) {
                    float a0 = acc[0][mi][nf][half * 2 + e];
                    float a1 = acc[1][mi][nf][half * 2 + e];
                    float a2 = acc[2][mi][nf][half * 2 + e];
                    if (MODE == 0) {
                        float r = sigm_(a0 + bA[nf][e]);
                        float z = sigm_(a1 + bB[nf][e]);
                        float nn = tanh_(a2 + bC2[nf][e] + r * bD[nf][e]);
                        res[e] = (1.f - z) * nn;
                    } else {
                        float hh = tanh_(a0 + bA[nf][e]);
                        float t  = sigm_(a1 + bB[nf][e]);
                        float cc = sigm_(a2 + bC2[nf][e]);
                        uint32_t hw = *(const uint32_t*)(hinHi + (size_t)m * HID + n);
                        uint32_t lw = *(const uint32_t*)(hinLo + (size_t)m * HID + n);
                        float hv = (e == 0) ? (bf2f(hw & 0xFFFFu) + bf2f(lw & 0xFFFFu))
                                            : (bf2f(hw >> 16) + bf2f(lw >> 16));
                        res[e] = hh * t + hv * (1.f - cc);
                    }
                }
                if (WSPLIT) {
                    uint32_t h0 = f2bf(res[0]), h1 = f2bf(res[1]);
                    uint32_t l0 = f2bf(res[0] - bf2f(h0)), l1 = f2bf(res[1] - bf2f(h1));
                    *(uint32_t*)(outHi + (size_t)m * HID + n) = h0 | (h1 << 16);
                    *(uint32_t*)(outLo + (size_t)m * HID + n) = l0 | (l1 << 16);
                } else {
                    *(float2*)(outF + (size_t)m * HID + n) = make_float2(res[0], res[1]);
                }
            }
        }
    }
}

extern "C" void kernel_launch(void* const* d_in, const int* in_sizes, int n_in,
                              void* d_out, int out_size)
{
    const float* x    = (const float*)d_in[0];
    const float* w_ih = (const float*)d_in[1];
    const float* b_ih = (const float*)d_in[3];
    const float* b_hh = (const float*)d_in[4];
    const float* WH   = (const float*)d_in[5];
    const float* bH   = (const float*)d_in[6];
    const float* WT   = (const float*)d_in[7];
    const float* bT   = (const float*)d_in[8];
    const float* WC   = (const float*)d_in[9];
    const float* bC   = (const float*)d_in[10];
    float* out = (float*)d_out;

    static bool attrSet = false;
    if (!attrSet) {
        cudaFuncSetAttribute(rhn_mma<512, 0, 1>,  cudaFuncAttributeMaxDynamicSharedMemorySize, DSMEM_TOTAL);
        cudaFuncSetAttribute(rhn_mma<1024, 1, 1>, cudaFuncAttributeMaxDynamicSharedMemorySize, DSMEM_TOTAL);
        cudaFuncSetAttribute(rhn_mma<1024, 1, 0>, cudaFuncAttributeMaxDynamicSharedMemorySize, DSMEM_TOTAL);
        attrSet = true;
    }

    __nv_bfloat16 *xh, *xl, *wh, *wl, *WHh, *WHl, *WTh, *WTl, *WCh, *WCl;
    __nv_bfloat16 *hAh, *hAl, *hBh, *hBl;
    cudaGetSymbolAddress((void**)&xh, g_x_hi);   cudaGetSymbolAddress((void**)&xl, g_x_lo);
    cudaGetSymbolAddress((void**)&wh, g_w_hi);   cudaGetSymbolAddress((void**)&wl, g_w_lo);
    cudaGetSymbolAddress((void**)&WHh, g_WH_hi); cudaGetSymbolAddress((void**)&WHl, g_WH_lo);
    cudaGetSymbolAddress((void**)&WTh, g_WT_hi); cudaGetSymbolAddress((void**)&WTl, g_WT_lo);
    cudaGetSymbolAddress((void**)&WCh, g_WC_hi); cudaGetSymbolAddress((void**)&WCl, g_WC_lo);
    cudaGetSymbolAddress((void**)&hAh, g_hA_hi); cudaGetSymbolAddress((void**)&hAl, g_hA_lo);
    cudaGetSymbolAddress((void**)&hBh, g_hB_hi); cudaGetSymbolAddress((void**)&hBl, g_hB_lo);

    {
        int n4 = MROWS * 512 / 4;
        split4<<<(n4 + 255) / 256, 256>>>((const float4*)x, (uint2*)xh, (uint2*)xl, n4);
        n4 = 3 * HID * 512 / 4;
        split4<<<(n4 + 255) / 256, 256>>>((const float4*)w_ih, (uint2*)wh, (uint2*)wl, n4);
        n4 = 5 * HID * HID / 4;
        dim3 g((n4 + 255) / 256, 1, 3);
        split4w<<<g, 256>>>((const float4*)WH, (uint2*)WHh, (uint2*)WHl,
                            (const float4*)WT, (uint2*)WTh, (uint2*)WTl,
                            (const float4*)WC, (uint2*)WCh, (uint2*)WCl, n4);
    }

    dim3 grd(HID / 64, MROWS / 128);
    rhn_mma<512, 0, 1><<<grd, 256, DSMEM_TOTAL>>>(
        xh, xl,
        wh, wl,
        wh + (size_t)HID * 512, wl + (size_t)HID * 512,
        wh + (size_t)2 * HID * 512, wl + (size_t)2 * HID * 512,
        b_ih, b_hh, nullptr, nullptr, nullptr,
        nullptr, hAh, hAl);

    for (int s = 0; s < 5; s++) {
        size_t wo = (size_t)s * HID * HID;
        const __nv_bfloat16* ih = (s & 1) ? hBh : hAh;
        const __nv_bfloat16* il = (s & 1) ? hBl : hAl;
        __nv_bfloat16* oh = (s & 1) ? hAh : hBh;
        __nv_bfloat16* ol = (s & 1) ? hAl : hBl;
        if (s == 4)
            rhn_mma<1024, 1, 0><<<grd, 256, DSMEM_TOTAL>>>(
                ih, il, WHh + wo, WHl + wo, WTh + wo, WTl + wo, WCh + wo, WCl + wo,
                bH + s * HID, bT + s * HID, bC + s * HID,
                ih, il, out, nullptr, nullptr);
        else
            rhn_mma<1024, 1, 1><<<grd, 256, DSMEM_TOTAL>>>(
                ih, il, WHh + wo, WHl + wo, WTh + wo, WTl + wo, WCh + wo, WCl + wo,
                bH + s * HID, bT + s * HID, bC + s * HID,
                ih, il, nullptr, oh, ol);
    }
}

// round 7
// speedup vs baseline: 1.1075x; 1.1075x over previous
#include <cuda_runtime.h>
#include <cuda_bf16.h>
#include <cstdint>

#define HID 1024
#define MROWS 32768
#define STAGE 32768
#define NST 3
#define DSMEM_TOTAL (NST * STAGE)

// ---- static device scratch (allocation-free rule) ----
__device__ __align__(16) __nv_bfloat16 g_x_hi [(size_t)MROWS * 512];
__device__ __align__(16) __nv_bfloat16 g_x_lo [(size_t)MROWS * 512];
__device__ __align__(16) __nv_bfloat16 g_w_hi [(size_t)3 * HID * 512];
__device__ __align__(16) __nv_bfloat16 g_w_lo [(size_t)3 * HID * 512];
__device__ __align__(16) __nv_bfloat16 g_WH_hi[(size_t)5 * HID * HID];
__device__ __align__(16) __nv_bfloat16 g_WH_lo[(size_t)5 * HID * HID];
__device__ __align__(16) __nv_bfloat16 g_WT_hi[(size_t)5 * HID * HID];
__device__ __align__(16) __nv_bfloat16 g_WT_lo[(size_t)5 * HID * HID];
__device__ __align__(16) __nv_bfloat16 g_WC_hi[(size_t)5 * HID * HID];
__device__ __align__(16) __nv_bfloat16 g_WC_lo[(size_t)5 * HID * HID];
__device__ __align__(16) __nv_bfloat16 g_hA_hi[(size_t)MROWS * HID];
__device__ __align__(16) __nv_bfloat16 g_hA_lo[(size_t)MROWS * HID];
__device__ __align__(16) __nv_bfloat16 g_hB_hi[(size_t)MROWS * HID];
__device__ __align__(16) __nv_bfloat16 g_hB_lo[(size_t)MROWS * HID];

// ---- helpers ----
__device__ __forceinline__ uint32_t smem_u32(const void* p) {
    uint32_t a;
    asm("{ .reg .u64 t; cvta.to.shared.u64 t, %1; cvt.u32.u64 %0, t; }" : "=r"(a) : "l"(p));
    return a;
}
__device__ __forceinline__ void cpa16(uint32_t s, const void* g) {
    asm volatile("cp.async.cg.shared.global [%0], [%1], 16;" :: "r"(s), "l"(g));
}
__device__ __forceinline__ void cpa_commit() {
    asm volatile("cp.async.commit_group;" ::: "memory");
}
__device__ __forceinline__ void cpa_wait1() {
    asm volatile("cp.async.wait_group 1;" ::: "memory");
}
__device__ __forceinline__ void ldsm4(uint32_t* r, uint32_t a) {
    asm volatile("ldmatrix.sync.aligned.m8n8.x4.shared.b16 {%0,%1,%2,%3}, [%4];"
                 : "=r"(r[0]), "=r"(r[1]), "=r"(r[2]), "=r"(r[3]) : "r"(a));
}
__device__ __forceinline__ void mma16816(float* d, const uint32_t* a, uint32_t b0, uint32_t b1) {
    asm volatile(
        "mma.sync.aligned.m16n8k16.row.col.f32.bf16.bf16.f32 "
        "{%0,%1,%2,%3}, {%4,%5,%6,%7}, {%8,%9}, {%0,%1,%2,%3};"
        : "+f"(d[0]), "+f"(d[1]), "+f"(d[2]), "+f"(d[3])
        : "r"(a[0]), "r"(a[1]), "r"(a[2]), "r"(a[3]), "r"(b0), "r"(b1));
}
// swizzled byte offset of 16B chunk (row r, chunk c in 0..3) of a k32-wide tile
__device__ __forceinline__ uint32_t swz(int r, int c) {
    return (uint32_t)((r >> 1) * 128 + (r & 1) * 64 + ((c ^ ((r >> 1) & 3)) << 4));
}
__device__ __forceinline__ float sigm_(float x) { return __fdividef(1.f, 1.f + __expf(-x)); }
__device__ __forceinline__ float tanh_(float x) {
    float ax = fabsf(x), e = __expf(-2.f * ax);
    float t = __fdividef(1.f - e, 1.f + e);
    return x >= 0.f ? t : -t;
}
__device__ __forceinline__ float bf2f(uint32_t b) { return __uint_as_float(b << 16); }
__device__ __forceinline__ uint32_t f2bf(float f) {
    return (uint32_t)__bfloat16_as_ushort(__float2bfloat16(f));
}

// ---- split fp32 -> (hi, lo) bf16 ----
__global__ void split4(const float4* __restrict__ src, uint2* __restrict__ hi,
                       uint2* __restrict__ lo, int n4) {
    int i = blockIdx.x * blockDim.x + threadIdx.x;
    if (i >= n4) return;
    float4 v = src[i];
    float vv[4] = {v.x, v.y, v.z, v.w};
    uint32_t h[4], l[4];
#pragma unroll
    for (int k = 0; k < 4; k++) {
        h[k] = f2bf(vv[k]);
        l[k] = f2bf(vv[k] - bf2f(h[k]));
    }
    hi[i] = make_uint2(h[0] | (h[1] << 16), h[2] | (h[3] << 16));
    lo[i] = make_uint2(l[0] | (l[1] << 16), l[2] | (l[3] << 16));
}

__global__ void split4w(const float4* __restrict__ s0, uint2* __restrict__ h0, uint2* __restrict__ l0,
                        const float4* __restrict__ s1, uint2* __restrict__ h1, uint2* __restrict__ l1,
                        const float4* __restrict__ s2, uint2* __restrict__ h2, uint2* __restrict__ l2,
                        int n4) {
    int i = blockIdx.x * blockDim.x + threadIdx.x;
    if (i >= n4) return;
    const float4* src = blockIdx.z == 0 ? s0 : (blockIdx.z == 1 ? s1 : s2);
    uint2* hi = blockIdx.z == 0 ? h0 : (blockIdx.z == 1 ? h1 : h2);
    uint2* lo = blockIdx.z == 0 ? l0 : (blockIdx.z == 1 ? l1 : l2);
    float4 v = src[i];
    float vv[4] = {v.x, v.y, v.z, v.w};
    uint32_t h[4], l[4];
#pragma unroll
    for (int k = 0; k < 4; k++) {
        h[k] = f2bf(vv[k]);
        l[k] = f2bf(vv[k] - bf2f(h[k]));
    }
    hi[i] = make_uint2(h[0] | (h[1] << 16), h[2] | (h[3] << 16));
    lo[i] = make_uint2(l[0] | (l[1] << 16), l[2] | (l[3] << 16));
}

// ---- fused 3-gate mma.sync GEMM + epilogue ----
// CTA tile: M=64, N=64 per gate, 3 gates. 256 threads, 8 warps 2m x 4n:
// wm = wid&1 (32 rows), wn = wid>>1 (16 cols). 2 CTAs/SM.
// smem stage (32KB): Ahi[0,4K) Alo[4K,8K) B[8K+(g*2+t)*4K).
template<int KF, int MODE, int WSPLIT>
__global__ void __launch_bounds__(256, 2)
rhn_mma(const __nv_bfloat16* __restrict__ Ahi, const __nv_bfloat16* __restrict__ Alo,
        const __nv_bfloat16* __restrict__ B0hi, const __nv_bfloat16* __restrict__ B0lo,
        const __nv_bfloat16* __restrict__ B1hi, const __nv_bfloat16* __restrict__ B1lo,
        const __nv_bfloat16* __restrict__ B2hi, const __nv_bfloat16* __restrict__ B2lo,
        const float* __restrict__ e0, const float* __restrict__ e1, const float* __restrict__ e2,
        const __nv_bfloat16* __restrict__ hinHi, const __nv_bfloat16* __restrict__ hinLo,
        float* __restrict__ outF,
        __nv_bfloat16* __restrict__ outHi, __nv_bfloat16* __restrict__ outLo)
{
    constexpr int NK = KF / 32;
    extern __shared__ __align__(128) uint8_t smemraw[];
    const uint32_t sbase = smem_u32(smemraw);

    const int tid = threadIdx.x;
    const int lane = tid & 31;
    const int wm = (tid >> 5) & 1;
    const int wn = tid >> 6;
    const int m0 = blockIdx.y * 64;
    const int n0 = blockIdx.x * 64;

    // ---- producer: 8 x 16B cp.async per thread per stage ----
    const char* cp[8];
    uint32_t so[8];
    {
        const int pr = tid >> 2;    // 0..63
        const int pc = tid & 3;     // 16B chunk in k32
        cp[0] = (const char*)(Ahi + (size_t)(m0 + pr) * KF + pc * 8);
        cp[1] = (const char*)(Alo + (size_t)(m0 + pr) * KF + pc * 8);
        so[0] = swz(pr, pc);
        so[1] = 4096u + swz(pr, pc);
        const __nv_bfloat16* bp[6] = {B0hi, B0lo, B1hi, B1lo, B2hi, B2lo};
#pragma unroll
        for (int t = 0; t < 6; t++) {
            cp[2 + t] = (const char*)(bp[t] + (size_t)(n0 + pr) * KF + pc * 8);
            so[2 + t] = 8192u + t * 4096u + swz(pr, pc);
        }
    }

    // ---- consumer: precompute ldmatrix offsets ----
    const int mat = lane >> 3;
    const int khf = lane >> 4;
    uint32_t aoff[2][2];   // [mi][ks] (hi; lo = +4096)
    uint32_t boff[2];      // [ks] (+8192 + (g*2+t)*4096)
#pragma unroll
    for (int mi = 0; mi < 2; mi++) {
        int r = wm * 32 + mi * 16 + (mat & 1) * 8 + (lane & 7);
        uint32_t base = (uint32_t)((r >> 1) * 128 + (r & 1) * 64);
        int sw = (r >> 1) & 3;
#pragma unroll
        for (int ks = 0; ks < 2; ks++)
            aoff[mi][ks] = base + (uint32_t)(((ks * 2 + khf) ^ sw) << 4);
    }
    {
        int r = wn * 16 + (mat & 1) * 8 + (lane & 7);
        uint32_t base = (uint32_t)((r >> 1) * 128 + (r & 1) * 64);
        int sw = (r >> 1) & 3;
#pragma unroll
        for (int ks = 0; ks < 2; ks++)
            boff[ks] = base + (uint32_t)(((ks * 2 + khf) ^ sw) << 4);
    }

    float acc[3][2][2][4];
#pragma unroll
    for (int g = 0; g < 3; g++)
#pragma unroll
        for (int mi = 0; mi < 2; mi++)
#pragma unroll
            for (int nf = 0; nf < 2; nf++)
#pragma unroll
                for (int e = 0; e < 4; e++) acc[g][mi][nf][e] = 0.f;

    // preload stages 0,1
#pragma unroll
    for (int s = 0; s < 2; s++) {
        uint32_t sb_ = sbase + s * STAGE;
#pragma unroll
        for (int j = 0; j < 8; j++) cpa16(sb_ + so[j], cp[j] + (size_t)s * 64);
        cpa_commit();
    }
#pragma unroll
    for (int j = 0; j < 8; j++) cp[j] += 128;   // at chunk 2

    uint32_t rd = sbase;
    uint32_t wr = sbase + 2u * STAGE;
    const uint32_t send = sbase + 3u * STAGE;

    for (int i = 0; i < NK; i++) {
        cpa_wait1();       // stage i landed (in flight: i, i+1)
        __syncthreads();   // also: slot (i+2)%3 == (i-1)%3 readers are done

        if (i + 2 < NK) {
#pragma unroll
            for (int j = 0; j < 8; j++) { cpa16(wr + so[j], cp[j]); cp[j] += 64; }
        }
        cpa_commit();

#pragma unroll
        for (int ks = 0; ks < 2; ks++) {
            uint32_t aH[8], aL[8];
#pragma unroll
            for (int mi = 0; mi < 2; mi++) {
                uint32_t ad = rd + aoff[mi][ks];
                ldsm4(&aH[mi * 4], ad);
                ldsm4(&aL[mi * 4], ad + 4096u);
            }
            const uint32_t bb = rd + boff[ks] + 8192u;
#pragma unroll
            for (int g = 0; g < 3; g++) {
                uint32_t bh[4], bl[4];
                ldsm4(bh, bb + (g * 2 + 0) * 4096u);
                ldsm4(bl, bb + (g * 2 + 1) * 4096u);
#pragma unroll
                for (int mi = 0; mi < 2; mi++) {
                    mma16816(acc[g][mi][0], &aH[mi * 4], bh[0], bh[2]);
                    mma16816(acc[g][mi][1], &aH[mi * 4], bh[1], bh[3]);
                    mma16816(acc[g][mi][0], &aH[mi * 4], bl[0], bl[2]);
                    mma16816(acc[g][mi][1], &aH[mi * 4], bl[1], bl[3]);
                    mma16816(acc[g][mi][0], &aL[mi * 4], bh[0], bh[2]);
                    mma16816(acc[g][mi][1], &aL[mi * 4], bh[1], bh[3]);
                }
            }
        }
        rd += STAGE; if (rd == send) rd = sbase;
        wr += STAGE; if (wr == send) wr = sbase;
    }

    // ---- epilogue ----
    float bA[2][2], bB[2][2], bC2[2][2], bD[2][2];
#pragma unroll
    for (int nf = 0; nf < 2; nf++) {
        int n = n0 + wn * 16 + nf * 8 + (lane & 3) * 2;
        if (MODE == 0) {
            float2 i0 = *(const float2*)&e0[n],         h0 = *(const float2*)&e1[n];
            float2 i1 = *(const float2*)&e0[HID + n],   h1 = *(const float2*)&e1[HID + n];
            float2 i2 = *(const float2*)&e0[2*HID + n], h2 = *(const float2*)&e1[2*HID + n];
            bA[nf][0] = i0.x + h0.x; bA[nf][1] = i0.y + h0.y;
            bB[nf][0] = i1.x + h1.x; bB[nf][1] = i1.y + h1.y;
            bC2[nf][0] = i2.x;       bC2[nf][1] = i2.y;
            bD[nf][0] = h2.x;        bD[nf][1] = h2.y;
        } else {
            float2 v0 = *(const float2*)&e0[n];
            float2 v1 = *(const float2*)&e1[n];
            float2 v2 = *(const float2*)&e2[n];
            bA[nf][0] = v0.x; bA[nf][1] = v0.y;
            bB[nf][0] = v1.x; bB[nf][1] = v1.y;
            bC2[nf][0] = v2.x; bC2[nf][1] = v2.y;
        }
    }

#pragma unroll
    for (int mi = 0; mi < 2; mi++) {
#pragma unroll
        for (int half = 0; half < 2; half++) {
            const int m = m0 + wm * 32 + mi * 16 + (lane >> 2) + half * 8;
#pragma unroll
            for (int nf = 0; nf < 2; nf++) {
                const int n = n0 + wn * 16 + nf * 8 + (lane & 3) * 2;
                float res[2];
#pragma unroll
                for (int e = 0; e < 2; e++) {
                    float a0 = acc[0][mi][nf][half * 2 + e];
                    float a1 = acc[1][mi][nf][half * 2 + e];
                    float a2 = acc[2][mi][nf][half * 2 + e];
                    if (MODE == 0) {
                        float r = sigm_(a0 + bA[nf][e]);
                        float z = sigm_(a1 + bB[nf][e]);
                        float nn = tanh_(a2 + bC2[nf][e] + r * bD[nf][e]);
                        res[e] = (1.f - z) * nn;
                    } else {
                        float hh = tanh_(a0 + bA[nf][e]);
                        float t  = sigm_(a1 + bB[nf][e]);
                        float cc = sigm_(a2 + bC2[nf][e]);
                        uint32_t hw = *(const uint32_t*)(hinHi + (size_t)m * HID + n);
                        uint32_t lw = *(const uint32_t*)(hinLo + (size_t)m * HID + n);
                        float hv = (e == 0) ? (bf2f(hw & 0xFFFFu) + bf2f(lw & 0xFFFFu))
                                            : (bf2f(hw >> 16) + bf2f(lw >> 16));
                        res[e] = hh * t + hv * (1.f - cc);
                    }
                }
                if (WSPLIT) {
                    uint32_t h0 = f2bf(res[0]), h1 = f2bf(res[1]);
                    uint32_t l0 = f2bf(res[0] - bf2f(h0)), l1 = f2bf(res[1] - bf2f(h1));
                    *(uint32_t*)(outHi + (size_t)m * HID + n) = h0 | (h1 << 16);
                    *(uint32_t*)(outLo + (size_t)m * HID + n) = l0 | (l1 << 16);
                } else {
                    *(float2*)(outF + (size_t)m * HID + n) = make_float2(res[0], res[1]);
                }
            }
        }
    }
}

extern "C" void kernel_launch(void* const* d_in, const int* in_sizes, int n_in,
                              void* d_out, int out_size)
{
    const float* x    = (const float*)d_in[0];
    const float* w_ih = (const float*)d_in[1];
    const float* b_ih = (const float*)d_in[3];
    const float* b_hh = (const float*)d_in[4];
    const float* WH   = (const float*)d_in[5];
    const float* bH   = (const float*)d_in[6];
    const float* WT   = (const float*)d_in[7];
    const float* bT   = (const float*)d_in[8];
    const float* WC   = (const float*)d_in[9];
    const float* bC   = (const float*)d_in[10];
    float* out = (float*)d_out;

    static bool attrSet = false;
    if (!attrSet) {
        cudaFuncSetAttribute(rhn_mma<512, 0, 1>,  cudaFuncAttributeMaxDynamicSharedMemorySize, DSMEM_TOTAL);
        cudaFuncSetAttribute(rhn_mma<1024, 1, 1>, cudaFuncAttributeMaxDynamicSharedMemorySize, DSMEM_TOTAL);
        cudaFuncSetAttribute(rhn_mma<1024, 1, 0>, cudaFuncAttributeMaxDynamicSharedMemorySize, DSMEM_TOTAL);
        attrSet = true;
    }

    __nv_bfloat16 *xh, *xl, *wh, *wl, *WHh, *WHl, *WTh, *WTl, *WCh, *WCl;
    __nv_bfloat16 *hAh, *hAl, *hBh, *hBl;
    cudaGetSymbolAddress((void**)&xh, g_x_hi);   cudaGetSymbolAddress((void**)&xl, g_x_lo);
    cudaGetSymbolAddress((void**)&wh, g_w_hi);   cudaGetSymbolAddress((void**)&wl, g_w_lo);
    cudaGetSymbolAddress((void**)&WHh, g_WH_hi); cudaGetSymbolAddress((void**)&WHl, g_WH_lo);
    cudaGetSymbolAddress((void**)&WTh, g_WT_hi); cudaGetSymbolAddress((void**)&WTl, g_WT_lo);
    cudaGetSymbolAddress((void**)&WCh, g_WC_hi); cudaGetSymbolAddress((void**)&WCl, g_WC_lo);
    cudaGetSymbolAddress((void**)&hAh, g_hA_hi); cudaGetSymbolAddress((void**)&hAl, g_hA_lo);
    cudaGetSymbolAddress((void**)&hBh, g_hB_hi); cudaGetSymbolAddress((void**)&hBl, g_hB_lo);

    {
        int n4 = MROWS * 512 / 4;
        split4<<<(n4 + 255) / 256, 256>>>((const float4*)x, (uint2*)xh, (uint2*)xl, n4);
        n4 = 3 * HID * 512 / 4;
        split4<<<(n4 + 255) / 256, 256>>>((const float4*)w_ih, (uint2*)wh, (uint2*)wl, n4);
        n4 = 5 * HID * HID / 4;
        dim3 g((n4 + 255) / 256, 1, 3);
        split4w<<<g, 256>>>((const float4*)WH, (uint2*)WHh, (uint2*)WHl,
                            (const float4*)WT, (uint2*)WTh, (uint2*)WTl,
                            (const float4*)WC, (uint2*)WCh, (uint2*)WCl, n4);
    }

    dim3 grd(HID / 64, MROWS / 64);
    rhn_mma<512, 0, 1><<<grd, 256, DSMEM_TOTAL>>>(
        xh, xl,
        wh, wl,
        wh + (size_t)HID * 512, wl + (size_t)HID * 512,
        wh + (size_t)2 * HID * 512, wl + (size_t)2 * HID * 512,
        b_ih, b_hh, nullptr, nullptr, nullptr,
        nullptr, hAh, hAl);

    for (int s = 0; s < 5; s++) {
        size_t wo = (size_t)s * HID * HID;
        const __nv_bfloat16* ih = (s & 1) ? hBh : hAh;
        const __nv_bfloat16* il = (s & 1) ? hBl : hAl;
        __nv_bfloat16* oh = (s & 1) ? hAh : hBh;
        __nv_bfloat16* ol = (s & 1) ? hAl : hBl;
        if (s == 4)
            rhn_mma<1024, 1, 0><<<grd, 256, DSMEM_TOTAL>>>(
                ih, il, WHh + wo, WHl + wo, WTh + wo, WTl + wo, WCh + wo, WCl + wo,
                bH + s * HID, bT + s * HID, bC + s * HID,
                ih, il, out, nullptr, nullptr);
        else
            rhn_mma<1024, 1, 1><<<grd, 256, DSMEM_TOTAL>>>(
                ih, il, WHh + wo, WHl + wo, WTh + wo, WTl + wo, WCh + wo, WCl + wo,
                bH + s * HID, bT + s * HID, bC + s * HID,
                ih, il, nullptr, oh, ol);
    }
}

// round 8
// speedup vs baseline: 1.9167x; 1.7307x over previous
#include <cuda_runtime.h>
#include <cuda_fp16.h>
#include <cstdint>

#define HID 1024
#define MROWS 32768
#define STAGE 20480
#define NST 4
#define DSMEM_TOTAL (NST * STAGE)

// ---- static device scratch (allocation-free rule) ----
__device__ __align__(16) __half g_x16 [(size_t)MROWS * 512];
__device__ __align__(16) __half g_w16 [(size_t)3 * HID * 512];
__device__ __align__(16) __half g_WH16[(size_t)5 * HID * HID];
__device__ __align__(16) __half g_WT16[(size_t)5 * HID * HID];
__device__ __align__(16) __half g_WC16[(size_t)5 * HID * HID];
__device__ __align__(16) __half g_h16A[(size_t)MROWS * HID];
__device__ __align__(16) __half g_h16B[(size_t)MROWS * HID];
__device__ __align__(16) float  g_h32A[(size_t)MROWS * HID];
__device__ __align__(16) float  g_h32B[(size_t)MROWS * HID];

// ---- helpers ----
__device__ __forceinline__ uint32_t smem_u32(const void* p) {
    uint32_t a;
    asm("{ .reg .u64 t; cvta.to.shared.u64 t, %1; cvt.u32.u64 %0, t; }" : "=r"(a) : "l"(p));
    return a;
}
__device__ __forceinline__ void cpa16(uint32_t s, const void* g) {
    asm volatile("cp.async.cg.shared.global [%0], [%1], 16;" :: "r"(s), "l"(g));
}
__device__ __forceinline__ void cpa_commit() {
    asm volatile("cp.async.commit_group;" ::: "memory");
}
__device__ __forceinline__ void cpa_wait2() {
    asm volatile("cp.async.wait_group 2;" ::: "memory");
}
__device__ __forceinline__ void ldsm4(uint32_t* r, uint32_t a) {
    asm volatile("ldmatrix.sync.aligned.m8n8.x4.shared.b16 {%0,%1,%2,%3}, [%4];"
                 : "=r"(r[0]), "=r"(r[1]), "=r"(r[2]), "=r"(r[3]) : "r"(a));
}
__device__ __forceinline__ void mma16816(float* d, const uint32_t* a, uint32_t b0, uint32_t b1) {
    asm volatile(
        "mma.sync.aligned.m16n8k16.row.col.f32.f16.f16.f32 "
        "{%0,%1,%2,%3}, {%4,%5,%6,%7}, {%8,%9}, {%0,%1,%2,%3};"
        : "+f"(d[0]), "+f"(d[1]), "+f"(d[2]), "+f"(d[3])
        : "r"(a[0]), "r"(a[1]), "r"(a[2]), "r"(a[3]), "r"(b0), "r"(b1));
}
// swizzled byte offset of a 16B chunk (row r, chunk c in 0..3) of a k32 fp16 tile
__device__ __forceinline__ uint32_t swz(int r, int c) {
    return (uint32_t)((r >> 1) * 128 + (r & 1) * 64 + ((c ^ ((r >> 1) & 3)) << 4));
}
__device__ __forceinline__ float sigm_(float x) { return __fdividef(1.f, 1.f + __expf(-x)); }
__device__ __forceinline__ float tanh_(float x) {
    float ax = fabsf(x), e = __expf(-2.f * ax);
    float t = __fdividef(1.f - e, 1.f + e);
    return x >= 0.f ? t : -t;
}
__device__ __forceinline__ uint32_t f2h(float f) {
    return (uint32_t)__half_as_ushort(__float2half_rn(f));
}

// ---- fp32 -> fp16 convert (4 floats / thread) ----
__global__ void cvt4(const float4* __restrict__ src, uint2* __restrict__ dst, int n4) {
    int i = blockIdx.x * blockDim.x + threadIdx.x;
    if (i >= n4) return;
    float4 v = src[i];
    uint2 o;
    o.x = f2h(v.x) | (f2h(v.y) << 16);
    o.y = f2h(v.z) | (f2h(v.w) << 16);
    dst[i] = o;
}
__global__ void cvt4w(const float4* __restrict__ s0, uint2* __restrict__ d0,
                      const float4* __restrict__ s1, uint2* __restrict__ d1,
                      const float4* __restrict__ s2, uint2* __restrict__ d2, int n4) {
    int i = blockIdx.x * blockDim.x + threadIdx.x;
    if (i >= n4) return;
    const float4* src = blockIdx.z == 0 ? s0 : (blockIdx.z == 1 ? s1 : s2);
    uint2* dst = blockIdx.z == 0 ? d0 : (blockIdx.z == 1 ? d1 : d2);
    float4 v = src[i];
    uint2 o;
    o.x = f2h(v.x) | (f2h(v.y) << 16);
    o.y = f2h(v.z) | (f2h(v.w) << 16);
    dst[i] = o;
}

// ---- fused 3-gate fp16 mma.sync GEMM + epilogue ----
// CTA tile: M=128, N=64 per gate, 3 gates. 256 threads, 8 warps 2m x 4n:
// wm = wid&1 (64 rows, mi 0..3), wn = wid>>1 (16 cols). 2 CTAs/SM, 4-stage pipe.
// smem stage (20KB): A[0,8K) fp16 128x32; Bg at 8K + g*4K (64x32 each).
template<int KF, int MODE, int WRH>
__global__ void __launch_bounds__(256, 2)
rhn_h(const __half* __restrict__ Ah,
      const __half* __restrict__ B0, const __half* __restrict__ B1, const __half* __restrict__ B2,
      const float* __restrict__ e0, const float* __restrict__ e1, const float* __restrict__ e2,
      const float* __restrict__ hin32,
      float* __restrict__ outF, __half* __restrict__ outH, float* __restrict__ outH32)
{
    constexpr int NK = KF / 32;
    extern __shared__ __align__(128) uint8_t smemraw[];
    const uint32_t sbase = smem_u32(smemraw);

    const int tid = threadIdx.x;
    const int lane = tid & 31;
    const int wm = (tid >> 5) & 1;
    const int wn = tid >> 6;
    const int m0 = blockIdx.y * 128;
    const int n0 = blockIdx.x * 64;

    // ---- producer: 5 x 16B cp.async per thread per stage ----
    const char* cp[5];
    uint32_t so[5];
    {
        const int pr = tid >> 2;    // 0..63
        const int pc = tid & 3;     // 16B chunk within k32 (8 fp16)
        cp[0] = (const char*)(Ah + (size_t)(m0 + pr) * KF + pc * 8);
        cp[1] = (const char*)(Ah + (size_t)(m0 + 64 + pr) * KF + pc * 8);
        so[0] = swz(pr, pc);
        so[1] = swz(pr + 64, pc);
        const __half* bp[3] = {B0, B1, B2};
#pragma unroll
        for (int t = 0; t < 3; t++) {
            cp[2 + t] = (const char*)(bp[t] + (size_t)(n0 + pr) * KF + pc * 8);
            so[2 + t] = 8192u + t * 4096u + swz(pr, pc);
        }
    }

    // ---- consumer ldmatrix offsets (chunk-invariant) ----
    const int mat = lane >> 3;
    const int khf = lane >> 4;
    uint32_t aoff[4][2];   // [mi][ks]
    uint32_t boff[2];      // [ks]; per gate add 8192 + g*4096
#pragma unroll
    for (int mi = 0; mi < 4; mi++) {
        int r = wm * 64 + mi * 16 + (mat & 1) * 8 + (lane & 7);
        uint32_t base = (uint32_t)((r >> 1) * 128 + (r & 1) * 64);
        int sw = (r >> 1) & 3;
#pragma unroll
        for (int ks = 0; ks < 2; ks++)
            aoff[mi][ks] = base + (uint32_t)(((ks * 2 + khf) ^ sw) << 4);
    }
    {
        int r = wn * 16 + (mat & 1) * 8 + (lane & 7);
        uint32_t base = (uint32_t)((r >> 1) * 128 + (r & 1) * 64);
        int sw = (r >> 1) & 3;
#pragma unroll
        for (int ks = 0; ks < 2; ks++)
            boff[ks] = base + (uint32_t)(((ks * 2 + khf) ^ sw) << 4);
    }

    float acc[3][4][2][4];
#pragma unroll
    for (int g = 0; g < 3; g++)
#pragma unroll
        for (int mi = 0; mi < 4; mi++)
#pragma unroll
            for (int nf = 0; nf < 2; nf++)
#pragma unroll
                for (int e = 0; e < 4; e++) acc[g][mi][nf][e] = 0.f;

    // preload stages 0..2
#pragma unroll
    for (int s = 0; s < 3; s++) {
        uint32_t sb_ = sbase + s * STAGE;
#pragma unroll
        for (int j = 0; j < 5; j++) cpa16(sb_ + so[j], cp[j] + (size_t)s * 64);
        cpa_commit();
    }
#pragma unroll
    for (int j = 0; j < 5; j++) cp[j] += 192;   // at chunk 3

    uint32_t rd = sbase;
    uint32_t wr = sbase + 3u * STAGE;
    const uint32_t send = sbase + 4u * STAGE;

    for (int i = 0; i < NK; i++) {
        cpa_wait2();       // stage i landed
        __syncthreads();   // slot (i+3)&3 == (i-1)&3 readers done

        if (i + 3 < NK) {
#pragma unroll
            for (int j = 0; j < 5; j++) { cpa16(wr + so[j], cp[j]); cp[j] += 64; }
        }
        cpa_commit();

#pragma unroll
        for (int ks = 0; ks < 2; ks++) {
            uint32_t a4[16];
#pragma unroll
            for (int mi = 0; mi < 4; mi++) ldsm4(&a4[mi * 4], rd + aoff[mi][ks]);
            const uint32_t bb = rd + 8192u + boff[ks];
#pragma unroll
            for (int g = 0; g < 3; g++) {
                uint32_t b4[4];
                ldsm4(b4, bb + g * 4096u);
#pragma unroll
                for (int mi = 0; mi < 4; mi++) {
                    mma16816(acc[g][mi][0], &a4[mi * 4], b4[0], b4[2]);
                    mma16816(acc[g][mi][1], &a4[mi * 4], b4[1], b4[3]);
                }
            }
        }
        rd += STAGE; if (rd == send) rd = sbase;
        wr += STAGE; if (wr == send) wr = sbase;
    }

    // ---- epilogue ----
    float bA[2][2], bB[2][2], bC2[2][2], bD[2][2];
#pragma unroll
    for (int nf = 0; nf < 2; nf++) {
        int n = n0 + wn * 16 + nf * 8 + (lane & 3) * 2;
        if (MODE == 0) {
            float2 i0 = *(const float2*)&e0[n],         h0 = *(const float2*)&e1[n];
            float2 i1 = *(const float2*)&e0[HID + n],   h1 = *(const float2*)&e1[HID + n];
            float2 i2 = *(const float2*)&e0[2*HID + n], h2 = *(const float2*)&e1[2*HID + n];
            bA[nf][0] = i0.x + h0.x; bA[nf][1] = i0.y + h0.y;
            bB[nf][0] = i1.x + h1.x; bB[nf][1] = i1.y + h1.y;
            bC2[nf][0] = i2.x;       bC2[nf][1] = i2.y;
            bD[nf][0] = h2.x;        bD[nf][1] = h2.y;
        } else {
            float2 v0 = *(const float2*)&e0[n];
            float2 v1 = *(const float2*)&e1[n];
            float2 v2 = *(const float2*)&e2[n];
            bA[nf][0] = v0.x; bA[nf][1] = v0.y;
            bB[nf][0] = v1.x; bB[nf][1] = v1.y;
            bC2[nf][0] = v2.x; bC2[nf][1] = v2.y;
        }
    }

#pragma unroll
    for (int mi = 0; mi < 4; mi++) {
#pragma unroll
        for (int half = 0; half < 2; half++) {
            const int m = m0 + wm * 64 + mi * 16 + (lane >> 2) + half * 8;
#pragma unroll
            for (int nf = 0; nf < 2; nf++) {
                const int n = n0 + wn * 16 + nf * 8 + (lane & 3) * 2;
                float res[2];
                float2 hv = make_float2(0.f, 0.f);
                if (MODE == 1) hv = *(const float2*)(hin32 + (size_t)m * HID + n);
#pragma unroll
                for (int e = 0; e < 2; e++) {
                    float a0 = acc[0][mi][nf][half * 2 + e];
                    float a1 = acc[1][mi][nf][half * 2 + e];
                    float a2 = acc[2][mi][nf][half * 2 + e];
                    if (MODE == 0) {
                        float r = sigm_(a0 + bA[nf][e]);
                        float z = sigm_(a1 + bB[nf][e]);
                        float nn = tanh_(a2 + bC2[nf][e] + r * bD[nf][e]);
                        res[e] = (1.f - z) * nn;
                    } else {
                        float hh = tanh_(a0 + bA[nf][e]);
                        float t  = sigm_(a1 + bB[nf][e]);
                        float cc = sigm_(a2 + bC2[nf][e]);
                        float hi = (e == 0) ? hv.x : hv.y;
                        res[e] = hh * t + hi * (1.f - cc);
                    }
                }
                if (WRH) {
                    *(uint32_t*)(outH + (size_t)m * HID + n) = f2h(res[0]) | (f2h(res[1]) << 16);
                    *(float2*)(outH32 + (size_t)m * HID + n) = make_float2(res[0], res[1]);
                } else {
                    *(float2*)(outF + (size_t)m * HID + n) = make_float2(res[0], res[1]);
                }
            }
        }
    }
}

extern "C" void kernel_launch(void* const* d_in, const int* in_sizes, int n_in,
                              void* d_out, int out_size)
{
    const float* x    = (const float*)d_in[0];
    const float* w_ih = (const float*)d_in[1];
    const float* b_ih = (const float*)d_in[3];
    const float* b_hh = (const float*)d_in[4];
    const float* WH   = (const float*)d_in[5];
    const float* bH   = (const float*)d_in[6];
    const float* WT   = (const float*)d_in[7];
    const float* bT   = (const float*)d_in[8];
    const float* WC   = (const float*)d_in[9];
    const float* bC   = (const float*)d_in[10];
    float* out = (float*)d_out;

    static bool attrSet = false;
    if (!attrSet) {
        cudaFuncSetAttribute(rhn_h<512, 0, 1>,  cudaFuncAttributeMaxDynamicSharedMemorySize, DSMEM_TOTAL);
        cudaFuncSetAttribute(rhn_h<1024, 1, 1>, cudaFuncAttributeMaxDynamicSharedMemorySize, DSMEM_TOTAL);
        cudaFuncSetAttribute(rhn_h<1024, 1, 0>, cudaFuncAttributeMaxDynamicSharedMemorySize, DSMEM_TOTAL);
        attrSet = true;
    }

    __half *x16, *w16, *WH16, *WT16, *WC16, *h16A, *h16B;
    float *h32A, *h32B;
    cudaGetSymbolAddress((void**)&x16, g_x16);
    cudaGetSymbolAddress((void**)&w16, g_w16);
    cudaGetSymbolAddress((void**)&WH16, g_WH16);
    cudaGetSymbolAddress((void**)&WT16, g_WT16);
    cudaGetSymbolAddress((void**)&WC16, g_WC16);
    cudaGetSymbolAddress((void**)&h16A, g_h16A);
    cudaGetSymbolAddress((void**)&h16B, g_h16B);
    cudaGetSymbolAddress((void**)&h32A, g_h32A);
    cudaGetSymbolAddress((void**)&h32B, g_h32B);

    {
        int n4 = MROWS * 512 / 4;
        cvt4<<<(n4 + 255) / 256, 256>>>((const float4*)x, (uint2*)x16, n4);
        n4 = 3 * HID * 512 / 4;
        cvt4<<<(n4 + 255) / 256, 256>>>((const float4*)w_ih, (uint2*)w16, n4);
        n4 = 5 * HID * HID / 4;
        dim3 g((n4 + 255) / 256, 1, 3);
        cvt4w<<<g, 256>>>((const float4*)WH, (uint2*)WH16,
                          (const float4*)WT, (uint2*)WT16,
                          (const float4*)WC, (uint2*)WC16, n4);
    }

    dim3 grd(HID / 64, MROWS / 128);
    // GRU gate GEMM (K=512): x -> h (fp16 + fp32) into A buffers
    rhn_h<512, 0, 1><<<grd, 256, DSMEM_TOTAL>>>(
        x16,
        w16, w16 + (size_t)HID * 512, w16 + (size_t)2 * HID * 512,
        b_ih, b_hh, nullptr,
        nullptr, nullptr, h16A, h32A);

    // 5 highway micro-steps
    for (int s = 0; s < 5; s++) {
        size_t wo = (size_t)s * HID * HID;
        const __half* ih = (s & 1) ? h16B : h16A;
        const float* ih32 = (s & 1) ? h32B : h32A;
        __half* oh = (s & 1) ? h16A : h16B;
        float* oh32 = (s & 1) ? h32A : h32B;
        if (s == 4)
            rhn_h<1024, 1, 0><<<grd, 256, DSMEM_TOTAL>>>(
                ih, WH16 + wo, WT16 + wo, WC16 + wo,
                bH + s * HID, bT + s * HID, bC + s * HID,
                ih32, out, nullptr, nullptr);
        else
            rhn_h<1024, 1, 1><<<grd, 256, DSMEM_TOTAL>>>(
                ih, WH16 + wo, WT16 + wo, WC16 + wo,
                bH + s * HID, bT + s * HID, bC + s * HID,
                ih32, nullptr, oh, oh32);
    }
}

// round 9
// speedup vs baseline: 2.1848x; 1.1399x over previous
#include <cuda_runtime.h>
#include <cuda_fp16.h>
#include <cstdint>

#define HID 1024
#define MROWS 32768
#define STAGE 40960
#define DSMEM_TOTAL (2 * STAGE)

// ---- static device scratch (allocation-free rule) ----
__device__ __align__(16) __half g_x16 [(size_t)MROWS * 512];
__device__ __align__(16) __half g_w16 [(size_t)3 * HID * 512];
__device__ __align__(16) __half g_WH16[(size_t)5 * HID * HID];
__device__ __align__(16) __half g_WT16[(size_t)5 * HID * HID];
__device__ __align__(16) __half g_WC16[(size_t)5 * HID * HID];
__device__ __align__(16) __half g_h16A[(size_t)MROWS * HID];
__device__ __align__(16) __half g_h16B[(size_t)MROWS * HID];
__device__ __align__(16) float  g_h32A[(size_t)MROWS * HID];
__device__ __align__(16) float  g_h32B[(size_t)MROWS * HID];

// ---- helpers ----
__device__ __forceinline__ uint32_t smem_u32(const void* p) {
    uint32_t a;
    asm("{ .reg .u64 t; cvta.to.shared.u64 t, %1; cvt.u32.u64 %0, t; }" : "=r"(a) : "l"(p));
    return a;
}
__device__ __forceinline__ void cpa16(uint32_t s, const void* g) {
    asm volatile("cp.async.cg.shared.global [%0], [%1], 16;" :: "r"(s), "l"(g));
}
__device__ __forceinline__ void cpa_commit() {
    asm volatile("cp.async.commit_group;" ::: "memory");
}
__device__ __forceinline__ void cpa_wait1() {
    asm volatile("cp.async.wait_group 1;" ::: "memory");
}
__device__ __forceinline__ void ldsm4(uint32_t* r, uint32_t a) {
    asm volatile("ldmatrix.sync.aligned.m8n8.x4.shared.b16 {%0,%1,%2,%3}, [%4];"
                 : "=r"(r[0]), "=r"(r[1]), "=r"(r[2]), "=r"(r[3]) : "r"(a));
}
__device__ __forceinline__ void mma16816(float* d, const uint32_t* a, uint32_t b0, uint32_t b1) {
    asm volatile(
        "mma.sync.aligned.m16n8k16.row.col.f32.f16.f16.f32 "
        "{%0,%1,%2,%3}, {%4,%5,%6,%7}, {%8,%9}, {%0,%1,%2,%3};"
        : "+f"(d[0]), "+f"(d[1]), "+f"(d[2]), "+f"(d[3])
        : "r"(a[0]), "r"(a[1]), "r"(a[2]), "r"(a[3]), "r"(b0), "r"(b1));
}
// swizzled byte offset inside a k64 (128B-row) fp16 tile: row r, 16B chunk c (0..7)
__device__ __forceinline__ uint32_t swz64(int r, int c) {
    return (uint32_t)(r * 128 + ((c ^ (r & 7)) << 4));
}
__device__ __forceinline__ float sigm_(float x) { return __fdividef(1.f, 1.f + __expf(-x)); }
__device__ __forceinline__ float tanh_(float x) {
    float ax = fabsf(x), e = __expf(-2.f * ax);
    float t = __fdividef(1.f - e, 1.f + e);
    return x >= 0.f ? t : -t;
}
__device__ __forceinline__ uint32_t f2h(float f) {
    return (uint32_t)__half_as_ushort(__float2half_rn(f));
}

// ---- fp32 -> fp16 convert ----
__global__ void cvt4(const float4* __restrict__ src, uint2* __restrict__ dst, int n4) {
    int i = blockIdx.x * blockDim.x + threadIdx.x;
    if (i >= n4) return;
    float4 v = src[i];
    uint2 o;
    o.x = f2h(v.x) | (f2h(v.y) << 16);
    o.y = f2h(v.z) | (f2h(v.w) << 16);
    dst[i] = o;
}
__global__ void cvt4w(const float4* __restrict__ s0, uint2* __restrict__ d0,
                      const float4* __restrict__ s1, uint2* __restrict__ d1,
                      const float4* __restrict__ s2, uint2* __restrict__ d2, int n4) {
    int i = blockIdx.x * blockDim.x + threadIdx.x;
    if (i >= n4) return;
    const float4* src = blockIdx.z == 0 ? s0 : (blockIdx.z == 1 ? s1 : s2);
    uint2* dst = blockIdx.z == 0 ? d0 : (blockIdx.z == 1 ? d1 : d2);
    float4 v = src[i];
    uint2 o;
    o.x = f2h(v.x) | (f2h(v.y) << 16);
    o.y = f2h(v.z) | (f2h(v.w) << 16);
    dst[i] = o;
}

// ---- fused 3-gate fp16 mma.sync GEMM + epilogue ----
// CTA tile M=128, N=64 per gate, 3 gates. 256 thr, 8 warps 2m x 4n. 2 CTAs/SM.
// k64 chunks, 2-stage double buffer.
// smem stage (40KB): A[0,16K) 128x(k64); Bg at 16K + g*8K (64x(k64)).
template<int KF, int MODE, int WRH>
__global__ void __launch_bounds__(256, 2)
rhn_h(const __half* __restrict__ Ah,
      const __half* __restrict__ B0, const __half* __restrict__ B1, const __half* __restrict__ B2,
      const float* __restrict__ e0, const float* __restrict__ e1, const float* __restrict__ e2,
      const float* __restrict__ hin32,
      float* __restrict__ outF, __half* __restrict__ outH, float* __restrict__ outH32)
{
    constexpr int NK = KF / 64;
    extern __shared__ __align__(128) uint8_t smemraw[];
    const uint32_t sbase = smem_u32(smemraw);

    const int tid = threadIdx.x;
    const int lane = tid & 31;
    const int wm = (tid >> 5) & 1;
    const int wn = tid >> 6;
    const int m0 = blockIdx.y * 128;
    const int n0 = blockIdx.x * 64;

    // ---- producer mapping: 10 x cpa16 per thread per stage (4 A + 6 B) ----
    const char* gA;          uint32_t soA[4];
    const char* gB[3];       uint32_t soB[3][2];
    {
        const int pr = tid >> 1;            // 0..127  (A row)
        const int pa = (tid & 1) * 4;       // chunk base 0 or 4
        gA = (const char*)(Ah + (size_t)(m0 + pr) * KF + pa * 8);
#pragma unroll
        for (int j = 0; j < 4; j++) soA[j] = swz64(pr, pa + j);

        const int idx = tid * 2;            // 0..510
        const int br = idx >> 3;            // 0..63
        const int bc = idx & 7;             // even chunk
        const __half* bp[3] = {B0, B1, B2};
#pragma unroll
        for (int g = 0; g < 3; g++) {
            gB[g] = (const char*)(bp[g] + (size_t)(n0 + br) * KF + bc * 8);
            soB[g][0] = 16384u + g * 8192u + swz64(br, bc);
            soB[g][1] = 16384u + g * 8192u + swz64(br, bc + 1);
        }
    }

    // ---- consumer bases ----
    const int mat = lane >> 3;
    const int khf = lane >> 4;
    const int swl = lane & 7;
    uint32_t abase[4], bbase;
#pragma unroll
    for (int mi = 0; mi < 4; mi++)
        abase[mi] = (uint32_t)((wm * 64 + mi * 16 + (mat & 1) * 8 + swl) * 128);
    bbase = (uint32_t)((wn * 16 + (mat & 1) * 8 + swl) * 128) + 16384u;
    uint32_t cidx[4];
#pragma unroll
    for (int ks = 0; ks < 4; ks++)
        cidx[ks] = (uint32_t)(((ks * 2 + khf) ^ swl) << 4);

    float acc[3][4][2][4];
#pragma unroll
    for (int g = 0; g < 3; g++)
#pragma unroll
        for (int mi = 0; mi < 4; mi++)
#pragma unroll
            for (int nf = 0; nf < 2; nf++)
#pragma unroll
                for (int e = 0; e < 4; e++) acc[g][mi][nf][e] = 0.f;

#define ISSUE_TO(SB)                                                          \
    {                                                                         \
        _Pragma("unroll")                                                     \
        for (int j = 0; j < 4; j++) cpa16((SB) + soA[j], gA + j * 16);        \
        _Pragma("unroll")                                                     \
        for (int g = 0; g < 3; g++) {                                         \
            cpa16((SB) + soB[g][0], gB[g]);                                   \
            cpa16((SB) + soB[g][1], gB[g] + 16);                              \
        }                                                                     \
    }
#define ADV(BYTES)                                                            \
    { gA += (BYTES); gB[0] += (BYTES); gB[1] += (BYTES); gB[2] += (BYTES); }

    // preload chunks 0,1
    ISSUE_TO(sbase); cpa_commit(); ADV(128);
    ISSUE_TO(sbase + STAGE); cpa_commit(); ADV(128);

    uint32_t rd = sbase;

    for (int i = 0; i < NK; i++) {
        cpa_wait1();        // chunk i landed
        __syncthreads();

#pragma unroll
        for (int ks = 0; ks < 4; ks++) {
            uint32_t a4[16];
#pragma unroll
            for (int mi = 0; mi < 4; mi++) ldsm4(&a4[mi * 4], rd + abase[mi] + cidx[ks]);
            const uint32_t bb = rd + bbase + cidx[ks];
#pragma unroll
            for (int g = 0; g < 3; g++) {
                uint32_t b4[4];
                ldsm4(b4, bb + g * 8192u);
#pragma unroll
                for (int mi = 0; mi < 4; mi++) {
                    mma16816(acc[g][mi][0], &a4[mi * 4], b4[0], b4[2]);
                    mma16816(acc[g][mi][1], &a4[mi * 4], b4[1], b4[3]);
                }
            }
        }
        __syncthreads();    // all reads of this slot done

        if (i + 2 < NK) { ISSUE_TO(rd); ADV(128); }  // chunk i+2 reuses slot of i
        cpa_commit();
        rd ^= STAGE;
    }

    // ---- epilogue ----
    float bA[2][2], bB[2][2], bC2[2][2], bD[2][2];
#pragma unroll
    for (int nf = 0; nf < 2; nf++) {
        int n = n0 + wn * 16 + nf * 8 + (lane & 3) * 2;
        if (MODE == 0) {
            float2 i0 = *(const float2*)&e0[n],         h0 = *(const float2*)&e1[n];
            float2 i1 = *(const float2*)&e0[HID + n],   h1 = *(const float2*)&e1[HID + n];
            float2 i2 = *(const float2*)&e0[2*HID + n], h2 = *(const float2*)&e1[2*HID + n];
            bA[nf][0] = i0.x + h0.x; bA[nf][1] = i0.y + h0.y;
            bB[nf][0] = i1.x + h1.x; bB[nf][1] = i1.y + h1.y;
            bC2[nf][0] = i2.x;       bC2[nf][1] = i2.y;
            bD[nf][0] = h2.x;        bD[nf][1] = h2.y;
        } else {
            float2 v0 = *(const float2*)&e0[n];
            float2 v1 = *(const float2*)&e1[n];
            float2 v2 = *(const float2*)&e2[n];
            bA[nf][0] = v0.x; bA[nf][1] = v0.y;
            bB[nf][0] = v1.x; bB[nf][1] = v1.y;
            bC2[nf][0] = v2.x; bC2[nf][1] = v2.y;
        }
    }

#pragma unroll
    for (int mi = 0; mi < 4; mi++) {
#pragma unroll
        for (int half = 0; half < 2; half++) {
            const int m = m0 + wm * 64 + mi * 16 + (lane >> 2) + half * 8;
#pragma unroll
            for (int nf = 0; nf < 2; nf++) {
                const int n = n0 + wn * 16 + nf * 8 + (lane & 3) * 2;
                float res[2];
                float2 hv = make_float2(0.f, 0.f);
                if (MODE == 1) hv = *(const float2*)(hin32 + (size_t)m * HID + n);
#pragma unroll
                for (int e = 0; e < 2; e++) {
                    float a0 = acc[0][mi][nf][half * 2 + e];
                    float a1 = acc[1][mi][nf][half * 2 + e];
                    float a2 = acc[2][mi][nf][half * 2 + e];
                    if (MODE == 0) {
                        float r = sigm_(a0 + bA[nf][e]);
                        float z = sigm_(a1 + bB[nf][e]);
                        float nn = tanh_(a2 + bC2[nf][e] + r * bD[nf][e]);
                        res[e] = (1.f - z) * nn;
                    } else {
                        float hh = tanh_(a0 + bA[nf][e]);
                        float t  = sigm_(a1 + bB[nf][e]);
                        float cc = sigm_(a2 + bC2[nf][e]);
                        float hi = (e == 0) ? hv.x : hv.y;
                        res[e] = hh * t + hi * (1.f - cc);
                    }
                }
                if (WRH) {
                    *(uint32_t*)(outH + (size_t)m * HID + n) = f2h(res[0]) | (f2h(res[1]) << 16);
                    *(float2*)(outH32 + (size_t)m * HID + n) = make_float2(res[0], res[1]);
                } else {
                    *(float2*)(outF + (size_t)m * HID + n) = make_float2(res[0], res[1]);
                }
            }
        }
    }
}

extern "C" void kernel_launch(void* const* d_in, const int* in_sizes, int n_in,
                              void* d_out, int out_size)
{
    const float* x    = (const float*)d_in[0];
    const float* w_ih = (const float*)d_in[1];
    const float* b_ih = (const float*)d_in[3];
    const float* b_hh = (const float*)d_in[4];
    const float* WH   = (const float*)d_in[5];
    const float* bH   = (const float*)d_in[6];
    const float* WT   = (const float*)d_in[7];
    const float* bT   = (const float*)d_in[8];
    const float* WC   = (const float*)d_in[9];
    const float* bC   = (const float*)d_in[10];
    float* out = (float*)d_out;

    static bool attrSet = false;
    if (!attrSet) {
        cudaFuncSetAttribute(rhn_h<512, 0, 1>,  cudaFuncAttributeMaxDynamicSharedMemorySize, DSMEM_TOTAL);
        cudaFuncSetAttribute(rhn_h<1024, 1, 1>, cudaFuncAttributeMaxDynamicSharedMemorySize, DSMEM_TOTAL);
        cudaFuncSetAttribute(rhn_h<1024, 1, 0>, cudaFuncAttributeMaxDynamicSharedMemorySize, DSMEM_TOTAL);
        attrSet = true;
    }

    __half *x16, *w16, *WH16, *WT16, *WC16, *h16A, *h16B;
    float *h32A, *h32B;
    cudaGetSymbolAddress((void**)&x16, g_x16);
    cudaGetSymbolAddress((void**)&w16, g_w16);
    cudaGetSymbolAddress((void**)&WH16, g_WH16);
    cudaGetSymbolAddress((void**)&WT16, g_WT16);
    cudaGetSymbolAddress((void**)&WC16, g_WC16);
    cudaGetSymbolAddress((void**)&h16A, g_h16A);
    cudaGetSymbolAddress((void**)&h16B, g_h16B);
    cudaGetSymbolAddress((void**)&h32A, g_h32A);
    cudaGetSymbolAddress((void**)&h32B, g_h32B);

    {
        int n4 = MROWS * 512 / 4;
        cvt4<<<(n4 + 255) / 256, 256>>>((const float4*)x, (uint2*)x16, n4);
        n4 = 3 * HID * 512 / 4;
        cvt4<<<(n4 + 255) / 256, 256>>>((const float4*)w_ih, (uint2*)w16, n4);
        n4 = 5 * HID * HID / 4;
        dim3 g((n4 + 255) / 256, 1, 3);
        cvt4w<<<g, 256>>>((const float4*)WH, (uint2*)WH16,
                          (const float4*)WT, (uint2*)WT16,
                          (const float4*)WC, (uint2*)WC16, n4);
    }

    dim3 grd(HID / 64, MROWS / 128);
    rhn_h<512, 0, 1><<<grd, 256, DSMEM_TOTAL>>>(
        x16,
        w16, w16 + (size_t)HID * 512, w16 + (size_t)2 * HID * 512,
        b_ih, b_hh, nullptr,
        nullptr, nullptr, h16A, h32A);

    for (int s = 0; s < 5; s++) {
        size_t wo = (size_t)s * HID * HID;
        const __half* ih = (s & 1) ? h16B : h16A;
        const float* ih32 = (s & 1) ? h32B : h32A;
        __half* oh = (s & 1) ? h16A : h16B;
        float* oh32 = (s & 1) ? h32A : h32B;
        if (s == 4)
            rhn_h<1024, 1, 0><<<grd, 256, DSMEM_TOTAL>>>(
                ih, WH16 + wo, WT16 + wo, WC16 + wo,
                bH + s * HID, bT + s * HID, bC + s * HID,
                ih32, out, nullptr, nullptr);
        else
            rhn_h<1024, 1, 1><<<grd, 256, DSMEM_TOTAL>>>(
                ih, WH16 + wo, WT16 + wo, WC16 + wo,
                bH + s * HID, bT + s * HID, bC + s * HID,
                ih32, nullptr, oh, oh32);
    }
}

// round 10
// speedup vs baseline: 2.6417x; 1.2092x over previous
#include <cuda_runtime.h>
#include <cuda_fp16.h>
#include <cstdint>

#define HID 1024
#define MROWS 32768
#define STAGE 32768
#define DSMEM_TOTAL (3 * STAGE)

// ---- static device scratch (allocation-free rule) ----
__device__ __align__(16) __half g_x16 [(size_t)MROWS * 512];
__device__ __align__(16) __half g_w16 [(size_t)3 * HID * 512];
__device__ __align__(16) __half g_WH16[(size_t)5 * HID * HID];
__device__ __align__(16) __half g_WT16[(size_t)5 * HID * HID];
__device__ __align__(16) __half g_WC16[(size_t)5 * HID * HID];
__device__ __align__(16) __half g_h16A[(size_t)MROWS * HID];
__device__ __align__(16) __half g_h16B[(size_t)MROWS * HID];
__device__ __align__(16) float  g_h32A[(size_t)MROWS * HID];
__device__ __align__(16) float  g_h32B[(size_t)MROWS * HID];

// ---- helpers ----
__device__ __forceinline__ uint32_t smem_u32(const void* p) {
    uint32_t a;
    asm("{ .reg .u64 t; cvta.to.shared.u64 t, %1; cvt.u32.u64 %0, t; }" : "=r"(a) : "l"(p));
    return a;
}
__device__ __forceinline__ void cpa16(uint32_t s, const void* g) {
    asm volatile("cp.async.cg.shared.global [%0], [%1], 16;" :: "r"(s), "l"(g));
}
__device__ __forceinline__ void cpa_commit() {
    asm volatile("cp.async.commit_group;" ::: "memory");
}
__device__ __forceinline__ void cpa_wait1() {
    asm volatile("cp.async.wait_group 1;" ::: "memory");
}
__device__ __forceinline__ void ldsm4(uint32_t* r, uint32_t a) {
    asm volatile("ldmatrix.sync.aligned.m8n8.x4.shared.b16 {%0,%1,%2,%3}, [%4];"
                 : "=r"(r[0]), "=r"(r[1]), "=r"(r[2]), "=r"(r[3]) : "r"(a));
}
__device__ __forceinline__ void mma16816(float* d, const uint32_t* a, uint32_t b0, uint32_t b1) {
    asm volatile(
        "mma.sync.aligned.m16n8k16.row.col.f32.f16.f16.f32 "
        "{%0,%1,%2,%3}, {%4,%5,%6,%7}, {%8,%9}, {%0,%1,%2,%3};"
        : "+f"(d[0]), "+f"(d[1]), "+f"(d[2]), "+f"(d[3])
        : "r"(a[0]), "r"(a[1]), "r"(a[2]), "r"(a[3]), "r"(b0), "r"(b1));
}
// swizzled byte offset inside a k64 (128B-row) fp16 tile: row r, 16B chunk c (0..7)
__device__ __forceinline__ uint32_t swz64(int r, int c) {
    return (uint32_t)(r * 128 + ((c ^ (r & 7)) << 4));
}
__device__ __forceinline__ float sigm_(float x) { return __fdividef(1.f, 1.f + __expf(-x)); }
__device__ __forceinline__ float tanh_(float x) {
    float ax = fabsf(x), e = __expf(-2.f * ax);
    float t = __fdividef(1.f - e, 1.f + e);
    return x >= 0.f ? t : -t;
}
__device__ __forceinline__ uint32_t f2h(float f) {
    return (uint32_t)__half_as_ushort(__float2half_rn(f));
}

// ---- fp32 -> fp16 convert ----
__global__ void cvt4(const float4* __restrict__ src, uint2* __restrict__ dst, int n4) {
    int i = blockIdx.x * blockDim.x + threadIdx.x;
    if (i >= n4) return;
    float4 v = src[i];
    uint2 o;
    o.x = f2h(v.x) | (f2h(v.y) << 16);
    o.y = f2h(v.z) | (f2h(v.w) << 16);
    dst[i] = o;
}
__global__ void cvt4w(const float4* __restrict__ s0, uint2* __restrict__ d0,
                      const float4* __restrict__ s1, uint2* __restrict__ d1,
                      const float4* __restrict__ s2, uint2* __restrict__ d2, int n4) {
    int i = blockIdx.x * blockDim.x + threadIdx.x;
    if (i >= n4) return;
    const float4* src = blockIdx.z == 0 ? s0 : (blockIdx.z == 1 ? s1 : s2);
    uint2* dst = blockIdx.z == 0 ? d0 : (blockIdx.z == 1 ? d1 : d2);
    float4 v = src[i];
    uint2 o;
    o.x = f2h(v.x) | (f2h(v.y) << 16);
    o.y = f2h(v.z) | (f2h(v.w) << 16);
    dst[i] = o;
}

// ---- fused 3-gate fp16 mma.sync GEMM + epilogue ----
// CTA tile M=64, N=64 per gate, 3 gates. 256 thr, 8 warps 2m x 4n. 2 CTAs/SM.
// k64 chunks, 3-stage pipeline, ONE __syncthreads per chunk.
// smem stage (32KB): A[0,8K) 64x(k64); Bg at 8K + g*8K (64x(k64)).
template<int KF, int MODE, int WRH>
__global__ void __launch_bounds__(256, 2)
rhn_h(const __half* __restrict__ Ah,
      const __half* __restrict__ B0, const __half* __restrict__ B1, const __half* __restrict__ B2,
      const float* __restrict__ e0, const float* __restrict__ e1, const float* __restrict__ e2,
      const float* __restrict__ hin32,
      float* __restrict__ outF, __half* __restrict__ outH, float* __restrict__ outH32)
{
    constexpr int NK = KF / 64;
    extern __shared__ __align__(128) uint8_t smemraw[];
    const uint32_t sbase = smem_u32(smemraw);

    const int tid = threadIdx.x;
    const int lane = tid & 31;
    const int wm = (tid >> 5) & 1;
    const int wn = tid >> 6;
    const int m0 = blockIdx.y * 64;
    const int n0 = blockIdx.x * 64;

    // ---- producer mapping: 8 x cpa16 per thread per stage (2 A + 6 B) ----
    const char* gA;
    const char* gB[3];
    uint32_t soA0, soA1, soB[3][2];
    {
        const int pr = tid >> 2;            // 0..63
        const int pc = (tid & 3) * 2;       // chunk 0,2,4,6
        gA = (const char*)(Ah + (size_t)(m0 + pr) * KF + pc * 8);
        soA0 = swz64(pr, pc);
        soA1 = swz64(pr, pc + 1);
        const __half* bp[3] = {B0, B1, B2};
#pragma unroll
        for (int g = 0; g < 3; g++) {
            gB[g] = (const char*)(bp[g] + (size_t)(n0 + pr) * KF + pc * 8);
            soB[g][0] = 8192u + g * 8192u + swz64(pr, pc);
            soB[g][1] = 8192u + g * 8192u + swz64(pr, pc + 1);
        }
    }

    // ---- consumer bases (swizzle idx == lane&7 for all our rows) ----
    const int mat = lane >> 3;
    const int khf = lane >> 4;
    const int swl = lane & 7;
    const uint32_t aoffb = (uint32_t)((wm * 32 + (mat & 1) * 8 + swl) * 128);
    const uint32_t boffb = 8192u + (uint32_t)((wn * 16 + (mat & 1) * 8 + swl) * 128);
    uint32_t cidx[4];
#pragma unroll
    for (int ks = 0; ks < 4; ks++)
        cidx[ks] = (uint32_t)(((ks * 2 + khf) ^ swl) << 4);

    float acc[3][2][2][4];
#pragma unroll
    for (int g = 0; g < 3; g++)
#pragma unroll
        for (int mi = 0; mi < 2; mi++)
#pragma unroll
            for (int nf = 0; nf < 2; nf++)
#pragma unroll
                for (int e = 0; e < 4; e++) acc[g][mi][nf][e] = 0.f;

#define ISSUE_TO(SB)                                                          \
    {                                                                         \
        cpa16((SB) + soA0, gA);                                               \
        cpa16((SB) + soA1, gA + 16);                                          \
        _Pragma("unroll")                                                     \
        for (int g = 0; g < 3; g++) {                                         \
            cpa16((SB) + soB[g][0], gB[g]);                                   \
            cpa16((SB) + soB[g][1], gB[g] + 16);                              \
        }                                                                     \
    }
#define ADV()                                                                 \
    { gA += 128; gB[0] += 128; gB[1] += 128; gB[2] += 128; }

#define LOAD_KS(RD, KS, A, B)                                                 \
    {                                                                         \
        uint32_t ab_ = (RD) + aoffb + cidx[KS];                               \
        ldsm4((A), ab_);                                                      \
        ldsm4((A) + 4, ab_ + 2048u);                                          \
        uint32_t bb_ = (RD) + boffb + cidx[KS];                               \
        ldsm4((B), bb_);                                                      \
        ldsm4((B) + 4, bb_ + 8192u);                                          \
        ldsm4((B) + 8, bb_ + 16384u);                                         \
    }
#define MMA_KS(A, B)                                                          \
    {                                                                         \
        _Pragma("unroll")                                                     \
        for (int g = 0; g < 3; g++)                                           \
            _Pragma("unroll")                                                 \
            for (int mi = 0; mi < 2; mi++) {                                  \
                mma16816(acc[g][mi][0], (A) + mi * 4, (B)[g * 4 + 0], (B)[g * 4 + 2]); \
                mma16816(acc[g][mi][1], (A) + mi * 4, (B)[g * 4 + 1], (B)[g * 4 + 3]); \
            }                                                                 \
    }

    // preload chunks 0,1 into slots 0,1
    ISSUE_TO(sbase); cpa_commit(); ADV();
    ISSUE_TO(sbase + STAGE); cpa_commit(); ADV();

    uint32_t rd = sbase;
    uint32_t wr = sbase + 2u * STAGE;
    const uint32_t send = sbase + 3u * STAGE;

    for (int i = 0; i < NK; i++) {
        cpa_wait1();        // chunk i landed
        __syncthreads();    // + slot (i+2)%3 (= chunk i-1's) readers are done

        if (i + 2 < NK) { ISSUE_TO(wr); ADV(); }
        cpa_commit();

        uint32_t a0[8], a1[8], b0r[12], b1r[12];
        LOAD_KS(rd, 0, a0, b0r);
        LOAD_KS(rd, 1, a1, b1r);
        MMA_KS(a0, b0r);
        LOAD_KS(rd, 2, a0, b0r);
        MMA_KS(a1, b1r);
        LOAD_KS(rd, 3, a1, b1r);
        MMA_KS(a0, b0r);
        MMA_KS(a1, b1r);

        rd += STAGE; if (rd == send) rd = sbase;
        wr += STAGE; if (wr == send) wr = sbase;
    }

    // ---- epilogue ----
    float bA[2][2], bB[2][2], bC2[2][2], bD[2][2];
#pragma unroll
    for (int nf = 0; nf < 2; nf++) {
        int n = n0 + wn * 16 + nf * 8 + (lane & 3) * 2;
        if (MODE == 0) {
            float2 i0 = *(const float2*)&e0[n],         h0 = *(const float2*)&e1[n];
            float2 i1 = *(const float2*)&e0[HID + n],   h1 = *(const float2*)&e1[HID + n];
            float2 i2 = *(const float2*)&e0[2*HID + n], h2 = *(const float2*)&e1[2*HID + n];
            bA[nf][0] = i0.x + h0.x; bA[nf][1] = i0.y + h0.y;
            bB[nf][0] = i1.x + h1.x; bB[nf][1] = i1.y + h1.y;
            bC2[nf][0] = i2.x;       bC2[nf][1] = i2.y;
            bD[nf][0] = h2.x;        bD[nf][1] = h2.y;
        } else {
            float2 v0 = *(const float2*)&e0[n];
            float2 v1 = *(const float2*)&e1[n];
            float2 v2 = *(const float2*)&e2[n];
            bA[nf][0] = v0.x; bA[nf][1] = v0.y;
            bB[nf][0] = v1.x; bB[nf][1] = v1.y;
            bC2[nf][0] = v2.x; bC2[nf][1] = v2.y;
        }
    }

#pragma unroll
    for (int mi = 0; mi < 2; mi++) {
#pragma unroll
        for (int half = 0; half < 2; half++) {
            const int m = m0 + wm * 32 + mi * 16 + (lane >> 2) + half * 8;
#pragma unroll
            for (int nf = 0; nf < 2; nf++) {
                const int n = n0 + wn * 16 + nf * 8 + (lane & 3) * 2;
                float res[2];
                float2 hv = make_float2(0.f, 0.f);
                if (MODE == 1) hv = *(const float2*)(hin32 + (size_t)m * HID + n);
#pragma unroll
                for (int e = 0; e < 2; e++) {
                    float a0 = acc[0][mi][nf][half * 2 + e];
                    float a1 = acc[1][mi][nf][half * 2 + e];
                    float a2 = acc[2][mi][nf][half * 2 + e];
                    if (MODE == 0) {
                        float r = sigm_(a0 + bA[nf][e]);
                        float z = sigm_(a1 + bB[nf][e]);
                        float nn = tanh_(a2 + bC2[nf][e] + r * bD[nf][e]);
                        res[e] = (1.f - z) * nn;
                    } else {
                        float hh = tanh_(a0 + bA[nf][e]);
                        float t  = sigm_(a1 + bB[nf][e]);
                        float cc = sigm_(a2 + bC2[nf][e]);
                        float hi = (e == 0) ? hv.x : hv.y;
                        res[e] = hh * t + hi * (1.f - cc);
                    }
                }
                if (WRH) {
                    *(uint32_t*)(outH + (size_t)m * HID + n) = f2h(res[0]) | (f2h(res[1]) << 16);
                    *(float2*)(outH32 + (size_t)m * HID + n) = make_float2(res[0], res[1]);
                } else {
                    *(float2*)(outF + (size_t)m * HID + n) = make_float2(res[0], res[1]);
                }
            }
        }
    }
}

extern "C" void kernel_launch(void* const* d_in, const int* in_sizes, int n_in,
                              void* d_out, int out_size)
{
    const float* x    = (const float*)d_in[0];
    const float* w_ih = (const float*)d_in[1];
    const float* b_ih = (const float*)d_in[3];
    const float* b_hh = (const float*)d_in[4];
    const float* WH   = (const float*)d_in[5];
    const float* bH   = (const float*)d_in[6];
    const float* WT   = (const float*)d_in[7];
    const float* bT   = (const float*)d_in[8];
    const float* WC   = (const float*)d_in[9];
    const float* bC   = (const float*)d_in[10];
    float* out = (float*)d_out;

    static bool attrSet = false;
    if (!attrSet) {
        cudaFuncSetAttribute(rhn_h<512, 0, 1>,  cudaFuncAttributeMaxDynamicSharedMemorySize, DSMEM_TOTAL);
        cudaFuncSetAttribute(rhn_h<1024, 1, 1>, cudaFuncAttributeMaxDynamicSharedMemorySize, DSMEM_TOTAL);
        cudaFuncSetAttribute(rhn_h<1024, 1, 0>, cudaFuncAttributeMaxDynamicSharedMemorySize, DSMEM_TOTAL);
        attrSet = true;
    }

    __half *x16, *w16, *WH16, *WT16, *WC16, *h16A, *h16B;
    float *h32A, *h32B;
    cudaGetSymbolAddress((void**)&x16, g_x16);
    cudaGetSymbolAddress((void**)&w16, g_w16);
    cudaGetSymbolAddress((void**)&WH16, g_WH16);
    cudaGetSymbolAddress((void**)&WT16, g_WT16);
    cudaGetSymbolAddress((void**)&WC16, g_WC16);
    cudaGetSymbolAddress((void**)&h16A, g_h16A);
    cudaGetSymbolAddress((void**)&h16B, g_h16B);
    cudaGetSymbolAddress((void**)&h32A, g_h32A);
    cudaGetSymbolAddress((void**)&h32B, g_h32B);

    {
        int n4 = MROWS * 512 / 4;
        cvt4<<<(n4 + 255) / 256, 256>>>((const float4*)x, (uint2*)x16, n4);
        n4 = 3 * HID * 512 / 4;
        cvt4<<<(n4 + 255) / 256, 256>>>((const float4*)w_ih, (uint2*)w16, n4);
        n4 = 5 * HID * HID / 4;
        dim3 g((n4 + 255) / 256, 1, 3);
        cvt4w<<<g, 256>>>((const float4*)WH, (uint2*)WH16,
                          (const float4*)WT, (uint2*)WT16,
                          (const float4*)WC, (uint2*)WC16, n4);
    }

    dim3 grd(HID / 64, MROWS / 64);
    rhn_h<512, 0, 1><<<grd, 256, DSMEM_TOTAL>>>(
        x16,
        w16, w16 + (size_t)HID * 512, w16 + (size_t)2 * HID * 512,
        b_ih, b_hh, nullptr,
        nullptr, nullptr, h16A, h32A);

    for (int s = 0; s < 5; s++) {
        size_t wo = (size_t)s * HID * HID;
        const __half* ih = (s & 1) ? h16B : h16A;
        const float* ih32 = (s & 1) ? h32B : h32A;
        __half* oh = (s & 1) ? h16A : h16B;
        float* oh32 = (s & 1) ? h32A : h32B;
        if (s == 4)
            rhn_h<1024, 1, 0><<<grd, 256, DSMEM_TOTAL>>>(
                ih, WH16 + wo, WT16 + wo, WC16 + wo,
                bH + s * HID, bT + s * HID, bC + s * HID,
                ih32, out, nullptr, nullptr);
        else
            rhn_h<1024, 1, 1><<<grd, 256, DSMEM_TOTAL>>>(
                ih, WH16 + wo, WT16 + wo, WC16 + wo,
                bH + s * HID, bT + s * HID, bC + s * HID,
                ih32, nullptr, oh, oh32);
    }
}

// round 11
// speedup vs baseline: 2.6757x; 1.0129x over previous
#include <cuda_runtime.h>
#include <cuda_fp16.h>
#include <cstdint>

#define HID 1024
#define MROWS 32768
#define STAGE 32768
#define DSMEM_TOTAL (2 * STAGE)

// ---- static device scratch (allocation-free rule) ----
__device__ __align__(16) __half g_x16 [(size_t)MROWS * 512];
__device__ __align__(16) __half g_w16 [(size_t)3 * HID * 512];
__device__ __align__(16) __half g_WH16[(size_t)5 * HID * HID];
__device__ __align__(16) __half g_WT16[(size_t)5 * HID * HID];
__device__ __align__(16) __half g_WC16[(size_t)5 * HID * HID];
__device__ __align__(16) __half g_h16A[(size_t)MROWS * HID];
__device__ __align__(16) __half g_h16B[(size_t)MROWS * HID];
__device__ __align__(16) float  g_h32A[(size_t)MROWS * HID];
__device__ __align__(16) float  g_h32B[(size_t)MROWS * HID];

// ---- helpers ----
__device__ __forceinline__ uint32_t smem_u32(const void* p) {
    uint32_t a;
    asm("{ .reg .u64 t; cvta.to.shared.u64 t, %1; cvt.u32.u64 %0, t; }" : "=r"(a) : "l"(p));
    return a;
}
__device__ __forceinline__ void cpa16(uint32_t s, const void* g) {
    asm volatile("cp.async.cg.shared.global [%0], [%1], 16;" :: "r"(s), "l"(g));
}
__device__ __forceinline__ void cpa_commit() {
    asm volatile("cp.async.commit_group;" ::: "memory");
}
__device__ __forceinline__ void cpa_wait1() {
    asm volatile("cp.async.wait_group 1;" ::: "memory");
}
__device__ __forceinline__ void ldsm4(uint32_t* r, uint32_t a) {
    asm volatile("ldmatrix.sync.aligned.m8n8.x4.shared.b16 {%0,%1,%2,%3}, [%4];"
                 : "=r"(r[0]), "=r"(r[1]), "=r"(r[2]), "=r"(r[3]) : "r"(a));
}
__device__ __forceinline__ void mma16816(float* d, const uint32_t* a, uint32_t b0, uint32_t b1) {
    asm volatile(
        "mma.sync.aligned.m16n8k16.row.col.f32.f16.f16.f32 "
        "{%0,%1,%2,%3}, {%4,%5,%6,%7}, {%8,%9}, {%0,%1,%2,%3};"
        : "+f"(d[0]), "+f"(d[1]), "+f"(d[2]), "+f"(d[3])
        : "r"(a[0]), "r"(a[1]), "r"(a[2]), "r"(a[3]), "r"(b0), "r"(b1));
}
// swizzled byte offset inside a k64 (128B-row) fp16 tile: row r, 16B chunk c (0..7)
__device__ __forceinline__ uint32_t swz64(int r, int c) {
    return (uint32_t)(r * 128 + ((c ^ (r & 7)) << 4));
}
__device__ __forceinline__ float sigm_(float x) { return __fdividef(1.f, 1.f + __expf(-x)); }
__device__ __forceinline__ float tanh_(float x) {
    float ax = fabsf(x), e = __expf(-2.f * ax);
    float t = __fdividef(1.f - e, 1.f + e);
    return x >= 0.f ? t : -t;
}
__device__ __forceinline__ uint32_t f2h(float f) {
    return (uint32_t)__half_as_ushort(__float2half_rn(f));
}

// ---- fp32 -> fp16 convert ----
__global__ void cvt4(const float4* __restrict__ src, uint2* __restrict__ dst, int n4) {
    int i = blockIdx.x * blockDim.x + threadIdx.x;
    if (i >= n4) return;
    float4 v = src[i];
    uint2 o;
    o.x = f2h(v.x) | (f2h(v.y) << 16);
    o.y = f2h(v.z) | (f2h(v.w) << 16);
    dst[i] = o;
}
__global__ void cvt4w(const float4* __restrict__ s0, uint2* __restrict__ d0,
                      const float4* __restrict__ s1, uint2* __restrict__ d1,
                      const float4* __restrict__ s2, uint2* __restrict__ d2, int n4) {
    int i = blockIdx.x * blockDim.x + threadIdx.x;
    if (i >= n4) return;
    const float4* src = blockIdx.z == 0 ? s0 : (blockIdx.z == 1 ? s1 : s2);
    uint2* dst = blockIdx.z == 0 ? d0 : (blockIdx.z == 1 ? d1 : d2);
    float4 v = src[i];
    uint2 o;
    o.x = f2h(v.x) | (f2h(v.y) << 16);
    o.y = f2h(v.z) | (f2h(v.w) << 16);
    dst[i] = o;
}

// ---- fused 3-gate fp16 mma.sync GEMM + epilogue ----
// CTA tile M=64, N=64 per gate, 3 gates. 256 thr, 8 warps 2m x 4n. 3 CTAs/SM.
// k64 chunks, 2-stage double buffer (32KB/stage, 64KB total).
// smem stage: A[0,8K) 64x(k64); Bg at 8K + g*8K (64x(k64)).
template<int KF, int MODE, int WRH>
__global__ void __launch_bounds__(256, 3)
rhn_h(const __half* __restrict__ Ah,
      const __half* __restrict__ B0, const __half* __restrict__ B1, const __half* __restrict__ B2,
      const float* __restrict__ e0, const float* __restrict__ e1, const float* __restrict__ e2,
      const float* __restrict__ hin32,
      float* __restrict__ outF, __half* __restrict__ outH, float* __restrict__ outH32)
{
    constexpr int NK = KF / 64;
    extern __shared__ __align__(128) uint8_t smemraw[];
    const uint32_t sbase = smem_u32(smemraw);

    const int tid = threadIdx.x;
    const int lane = tid & 31;
    const int wm = (tid >> 5) & 1;
    const int wn = tid >> 6;
    const int m0 = blockIdx.y * 64;
    const int n0 = blockIdx.x * 64;

    // ---- producer mapping: 8 x cpa16 per thread per stage (2 A + 6 B) ----
    const char* gA;
    const char* gB[3];
    uint32_t soA0, soA1, soB[3][2];
    {
        const int pr = tid >> 2;            // 0..63
        const int pc = (tid & 3) * 2;       // chunk 0,2,4,6
        gA = (const char*)(Ah + (size_t)(m0 + pr) * KF + pc * 8);
        soA0 = swz64(pr, pc);
        soA1 = swz64(pr, pc + 1);
        const __half* bp[3] = {B0, B1, B2};
#pragma unroll
        for (int g = 0; g < 3; g++) {
            gB[g] = (const char*)(bp[g] + (size_t)(n0 + pr) * KF + pc * 8);
            soB[g][0] = 8192u + g * 8192u + swz64(pr, pc);
            soB[g][1] = 8192u + g * 8192u + swz64(pr, pc + 1);
        }
    }

    // ---- consumer bases ----
    const int mat = lane >> 3;
    const int khf = lane >> 4;
    const int swl = lane & 7;
    const uint32_t aoffb = (uint32_t)((wm * 32 + (mat & 1) * 8 + swl) * 128);
    const uint32_t boffb = 8192u + (uint32_t)((wn * 16 + (mat & 1) * 8 + swl) * 128);
    uint32_t cidx[4];
#pragma unroll
    for (int ks = 0; ks < 4; ks++)
        cidx[ks] = (uint32_t)(((ks * 2 + khf) ^ swl) << 4);

    float acc[3][2][2][4];
#pragma unroll
    for (int g = 0; g < 3; g++)
#pragma unroll
        for (int mi = 0; mi < 2; mi++)
#pragma unroll
            for (int nf = 0; nf < 2; nf++)
#pragma unroll
                for (int e = 0; e < 4; e++) acc[g][mi][nf][e] = 0.f;

#define ISSUE_TO(SB)                                                          \
    {                                                                         \
        cpa16((SB) + soA0, gA);                                               \
        cpa16((SB) + soA1, gA + 16);                                          \
        _Pragma("unroll")                                                     \
        for (int g = 0; g < 3; g++) {                                         \
            cpa16((SB) + soB[g][0], gB[g]);                                   \
            cpa16((SB) + soB[g][1], gB[g] + 16);                              \
        }                                                                     \
    }
#define ADV()                                                                 \
    { gA += 128; gB[0] += 128; gB[1] += 128; gB[2] += 128; }

    // preload chunks 0,1 into slots 0,1
    ISSUE_TO(sbase); cpa_commit(); ADV();
    ISSUE_TO(sbase + STAGE); cpa_commit(); ADV();

    uint32_t rd = sbase;

    for (int i = 0; i < NK; i++) {
        cpa_wait1();        // chunk i landed (i+1 may still be in flight)
        __syncthreads();

#pragma unroll
        for (int ks = 0; ks < 4; ks++) {
            uint32_t a4[8], b4[12];
            uint32_t ab_ = rd + aoffb + cidx[ks];
            ldsm4(a4, ab_);
            ldsm4(a4 + 4, ab_ + 2048u);
            uint32_t bb_ = rd + boffb + cidx[ks];
            ldsm4(b4, bb_);
            ldsm4(b4 + 4, bb_ + 8192u);
            ldsm4(b4 + 8, bb_ + 16384u);
#pragma unroll
            for (int g = 0; g < 3; g++)
#pragma unroll
                for (int mi = 0; mi < 2; mi++) {
                    mma16816(acc[g][mi][0], a4 + mi * 4, b4[g * 4 + 0], b4[g * 4 + 2]);
                    mma16816(acc[g][mi][1], a4 + mi * 4, b4[g * 4 + 1], b4[g * 4 + 3]);
                }
        }
        __syncthreads();    // this slot's readers are done

        if (i + 2 < NK) { ISSUE_TO(rd); ADV(); }   // chunk i+2 reuses slot of i
        cpa_commit();
        rd ^= STAGE;
    }

    // ---- epilogue ----
    float bA[2][2], bB[2][2], bC2[2][2], bD[2][2];
#pragma unroll
    for (int nf = 0; nf < 2; nf++) {
        int n = n0 + wn * 16 + nf * 8 + (lane & 3) * 2;
        if (MODE == 0) {
            float2 i0 = *(const float2*)&e0[n],         h0 = *(const float2*)&e1[n];
            float2 i1 = *(const float2*)&e0[HID + n],   h1 = *(const float2*)&e1[HID + n];
            float2 i2 = *(const float2*)&e0[2*HID + n], h2 = *(const float2*)&e1[2*HID + n];
            bA[nf][0] = i0.x + h0.x; bA[nf][1] = i0.y + h0.y;
            bB[nf][0] = i1.x + h1.x; bB[nf][1] = i1.y + h1.y;
            bC2[nf][0] = i2.x;       bC2[nf][1] = i2.y;
            bD[nf][0] = h2.x;        bD[nf][1] = h2.y;
        } else {
            float2 v0 = *(const float2*)&e0[n];
            float2 v1 = *(const float2*)&e1[n];
            float2 v2 = *(const float2*)&e2[n];
            bA[nf][0] = v0.x; bA[nf][1] = v0.y;
            bB[nf][0] = v1.x; bB[nf][1] = v1.y;
            bC2[nf][0] = v2.x; bC2[nf][1] = v2.y;
        }
    }

#pragma unroll
    for (int mi = 0; mi < 2; mi++) {
#pragma unroll
        for (int half = 0; half < 2; half++) {
            const int m = m0 + wm * 32 + mi * 16 + (lane >> 2) + half * 8;
#pragma unroll
            for (int nf = 0; nf < 2; nf++) {
                const int n = n0 + wn * 16 + nf * 8 + (lane & 3) * 2;
                float res[2];
                float2 hv = make_float2(0.f, 0.f);
                if (MODE == 1) hv = *(const float2*)(hin32 + (size_t)m * HID + n);
#pragma unroll
                for (int e = 0; e < 2; e++) {
                    float a0 = acc[0][mi][nf][half * 2 + e];
                    float a1 = acc[1][mi][nf][half * 2 + e];
                    float a2 = acc[2][mi][nf][half * 2 + e];
                    if (MODE == 0) {
                        float r = sigm_(a0 + bA[nf][e]);
                        float z = sigm_(a1 + bB[nf][e]);
                        float nn = tanh_(a2 + bC2[nf][e] + r * bD[nf][e]);
                        res[e] = (1.f - z) * nn;
                    } else {
                        float hh = tanh_(a0 + bA[nf][e]);
                        float t  = sigm_(a1 + bB[nf][e]);
                        float cc = sigm_(a2 + bC2[nf][e]);
                        float hi = (e == 0) ? hv.x : hv.y;
                        res[e] = hh * t + hi * (1.f - cc);
                    }
                }
                if (WRH) {
                    *(uint32_t*)(outH + (size_t)m * HID + n) = f2h(res[0]) | (f2h(res[1]) << 16);
                    *(float2*)(outH32 + (size_t)m * HID + n) = make_float2(res[0], res[1]);
                } else {
                    *(float2*)(outF + (size_t)m * HID + n) = make_float2(res[0], res[1]);
                }
            }
        }
    }
}

extern "C" void kernel_launch(void* const* d_in, const int* in_sizes, int n_in,
                              void* d_out, int out_size)
{
    const float* x    = (const float*)d_in[0];
    const float* w_ih = (const float*)d_in[1];
    const float* b_ih = (const float*)d_in[3];
    const float* b_hh = (const float*)d_in[4];
    const float* WH   = (const float*)d_in[5];
    const float* bH   = (const float*)d_in[6];
    const float* WT   = (const float*)d_in[7];
    const float* bT   = (const float*)d_in[8];
    const float* WC   = (const float*)d_in[9];
    const float* bC   = (const float*)d_in[10];
    float* out = (float*)d_out;

    static bool attrSet = false;
    if (!attrSet) {
        cudaFuncSetAttribute(rhn_h<512, 0, 1>,  cudaFuncAttributeMaxDynamicSharedMemorySize, DSMEM_TOTAL);
        cudaFuncSetAttribute(rhn_h<1024, 1, 1>, cudaFuncAttributeMaxDynamicSharedMemorySize, DSMEM_TOTAL);
        cudaFuncSetAttribute(rhn_h<1024, 1, 0>, cudaFuncAttributeMaxDynamicSharedMemorySize, DSMEM_TOTAL);
        attrSet = true;
    }

    __half *x16, *w16, *WH16, *WT16, *WC16, *h16A, *h16B;
    float *h32A, *h32B;
    cudaGetSymbolAddress((void**)&x16, g_x16);
    cudaGetSymbolAddress((void**)&w16, g_w16);
    cudaGetSymbolAddress((void**)&WH16, g_WH16);
    cudaGetSymbolAddress((void**)&WT16, g_WT16);
    cudaGetSymbolAddress((void**)&WC16, g_WC16);
    cudaGetSymbolAddress((void**)&h16A, g_h16A);
    cudaGetSymbolAddress((void**)&h16B, g_h16B);
    cudaGetSymbolAddress((void**)&h32A, g_h32A);
    cudaGetSymbolAddress((void**)&h32B, g_h32B);

    {
        int n4 = MROWS * 512 / 4;
        cvt4<<<(n4 + 255) / 256, 256>>>((const float4*)x, (uint2*)x16, n4);
        n4 = 3 * HID * 512 / 4;
        cvt4<<<(n4 + 255) / 256, 256>>>((const float4*)w_ih, (uint2*)w16, n4);
        n4 = 5 * HID * HID / 4;
        dim3 g((n4 + 255) / 256, 1, 3);
        cvt4w<<<g, 256>>>((const float4*)WH, (uint2*)WH16,
                          (const float4*)WT, (uint2*)WT16,
                          (const float4*)WC, (uint2*)WC16, n4);
    }

    dim3 grd(HID / 64, MROWS / 64);
    rhn_h<512, 0, 1><<<grd, 256, DSMEM_TOTAL>>>(
        x16,
        w16, w16 + (size_t)HID * 512, w16 + (size_t)2 * HID * 512,
        b_ih, b_hh, nullptr,
        nullptr, nullptr, h16A, h32A);

    for (int s = 0; s < 5; s++) {
        size_t wo = (size_t)s * HID * HID;
        const __half* ih = (s & 1) ? h16B : h16A;
        const float* ih32 = (s & 1) ? h32B : h32A;
        __half* oh = (s & 1) ? h16A : h16B;
        float* oh32 = (s & 1) ? h32A : h32B;
        if (s == 4)
            rhn_h<1024, 1, 0><<<grd, 256, DSMEM_TOTAL>>>(
                ih, WH16 + wo, WT16 + wo, WC16 + wo,
                bH + s * HID, bT + s * HID, bC + s * HID,
                ih32, out, nullptr, nullptr);
        else
            rhn_h<1024, 1, 1><<<grd, 256, DSMEM_TOTAL>>>(
                ih, WH16 + wo, WT16 + wo, WC16 + wo,
                bH + s * HID, bT + s * HID, bC + s * HID,
                ih32, nullptr, oh, oh32);
    }
}

// round 12
// speedup vs baseline: 3.4083x; 1.2738x over previous
#include <cuda_runtime.h>
#include <cuda_fp16.h>
#include <cstdint>

#define HID 1024
#define MROWS 32768
#define STAGE 32768
#define DSMEM_TOTAL (2 * STAGE)

// ---- static device scratch (allocation-free rule) ----
__device__ __align__(16) __half g_x16 [(size_t)MROWS * 512];
__device__ __align__(16) __half g_w16 [(size_t)3 * HID * 512];
__device__ __align__(16) __half g_WH16[(size_t)5 * HID * HID];
__device__ __align__(16) __half g_WT16[(size_t)5 * HID * HID];
__device__ __align__(16) __half g_WC16[(size_t)5 * HID * HID];
__device__ __align__(16) __half g_h16A[(size_t)MROWS * HID];
__device__ __align__(16) __half g_h16B[(size_t)MROWS * HID];

// ---- helpers ----
__device__ __forceinline__ uint32_t smem_u32(const void* p) {
    uint32_t a;
    asm("{ .reg .u64 t; cvta.to.shared.u64 t, %1; cvt.u32.u64 %0, t; }" : "=r"(a) : "l"(p));
    return a;
}
__device__ __forceinline__ void cpa16(uint32_t s, const void* g) {
    asm volatile("cp.async.cg.shared.global [%0], [%1], 16;" :: "r"(s), "l"(g));
}
__device__ __forceinline__ void cpa_commit() {
    asm volatile("cp.async.commit_group;" ::: "memory");
}
__device__ __forceinline__ void cpa_wait1() {
    asm volatile("cp.async.wait_group 1;" ::: "memory");
}
__device__ __forceinline__ void ldsm4(uint32_t* r, uint32_t a) {
    asm volatile("ldmatrix.sync.aligned.m8n8.x4.shared.b16 {%0,%1,%2,%3}, [%4];"
                 : "=r"(r[0]), "=r"(r[1]), "=r"(r[2]), "=r"(r[3]) : "r"(a));
}
__device__ __forceinline__ void mma16816(float* d, const uint32_t* a, uint32_t b0, uint32_t b1) {
    asm volatile(
        "mma.sync.aligned.m16n8k16.row.col.f32.f16.f16.f32 "
        "{%0,%1,%2,%3}, {%4,%5,%6,%7}, {%8,%9}, {%0,%1,%2,%3};"
        : "+f"(d[0]), "+f"(d[1]), "+f"(d[2]), "+f"(d[3])
        : "r"(a[0]), "r"(a[1]), "r"(a[2]), "r"(a[3]), "r"(b0), "r"(b1));
}
// swizzled byte offset inside a k64 (128B-row) fp16 tile: row r, 16B chunk c (0..7)
__device__ __forceinline__ uint32_t swz64(int r, int c) {
    return (uint32_t)(r * 128 + ((c ^ (r & 7)) << 4));
}
__device__ __forceinline__ float sigm_(float x) { return __fdividef(1.f, 1.f + __expf(-x)); }
__device__ __forceinline__ float tanh_(float x) {
    float ax = fabsf(x), e = __expf(-2.f * ax);
    float t = __fdividef(1.f - e, 1.f + e);
    return x >= 0.f ? t : -t;
}
__device__ __forceinline__ uint32_t f2h(float f) {
    return (uint32_t)__half_as_ushort(__float2half_rn(f));
}
__device__ __forceinline__ float h2f_lo(uint32_t u) {
    return __half2float(__ushort_as_half((unsigned short)(u & 0xFFFFu)));
}
__device__ __forceinline__ float h2f_hi(uint32_t u) {
    return __half2float(__ushort_as_half((unsigned short)(u >> 16)));
}

// ---- fp32 -> fp16 convert ----
__global__ void cvt4(const float4* __restrict__ src, uint2* __restrict__ dst, int n4) {
    int i = blockIdx.x * blockDim.x + threadIdx.x;
    if (i >= n4) return;
    float4 v = src[i];
    uint2 o;
    o.x = f2h(v.x) | (f2h(v.y) << 16);
    o.y = f2h(v.z) | (f2h(v.w) << 16);
    dst[i] = o;
}
__global__ void cvt4w(const float4* __restrict__ s0, uint2* __restrict__ d0,
                      const float4* __restrict__ s1, uint2* __restrict__ d1,
                      const float4* __restrict__ s2, uint2* __restrict__ d2, int n4) {
    int i = blockIdx.x * blockDim.x + threadIdx.x;
    if (i >= n4) return;
    const float4* src = blockIdx.z == 0 ? s0 : (blockIdx.z == 1 ? s1 : s2);
    uint2* dst = blockIdx.z == 0 ? d0 : (blockIdx.z == 1 ? d1 : d2);
    float4 v = src[i];
    uint2 o;
    o.x = f2h(v.x) | (f2h(v.y) << 16);
    o.y = f2h(v.z) | (f2h(v.w) << 16);
    dst[i] = o;
}

// ---- fused 3-gate fp16 mma.sync GEMM + epilogue ----
// CTA tile M=64, N=64 per gate, 3 gates. 128 threads, 4 warps.
// Warp w = n-group (16 cols); each warp covers ALL 64 M-rows (mi=0..3).
// B LDSM redundancy = 1, A redundancy = 4. 3 CTAs/SM.
// k64 chunks, 2-stage double buffer. smem stage: A[0,8K); Bg at 8K+g*8K.
template<int KF, int MODE, int WRH>
__global__ void __launch_bounds__(128, 3)
rhn_h(const __half* __restrict__ Ah,
      const __half* __restrict__ B0, const __half* __restrict__ B1, const __half* __restrict__ B2,
      const float* __restrict__ e0, const float* __restrict__ e1, const float* __restrict__ e2,
      const __half* __restrict__ hin,
      float* __restrict__ outF, __half* __restrict__ outH)
{
    constexpr int NK = KF / 64;
    constexpr int JSTRIDE = 16 * KF * 2;   // 16 rows in bytes
    extern __shared__ __align__(128) uint8_t smemraw[];
    const uint32_t sbase = smem_u32(smemraw);

    const int tid = threadIdx.x;
    const int lane = tid & 31;
    const int w = tid >> 5;            // warp = n-group 0..3
    const int m0 = blockIdx.y * 64;
    const int n0 = blockIdx.x * 64;

    // ---- producer mapping: 16 x cpa16 per thread per stage ----
    // thread: base row br = tid>>3 (0..15), chunk c = tid&7. j in 0..3 adds 16 rows.
    const int br = tid >> 3;
    const int pc = tid & 7;
    const char* gA = (const char*)(Ah + (size_t)(m0 + br) * KF + pc * 8);
    const char* gB[3];
    {
        const __half* bp[3] = {B0, B1, B2};
#pragma unroll
        for (int g = 0; g < 3; g++)
            gB[g] = (const char*)(bp[g] + (size_t)(n0 + br) * KF + pc * 8);
    }
    // swz64(br + 16j, c) = swz64(br, c) + j*2048  (16j doesn't change r&7)
    const uint32_t soA = swz64(br, pc);

    // ---- consumer bases ----
    const int mat = lane >> 3;
    const int khf = lane >> 4;
    const int swl = lane & 7;
    uint32_t aoffb[4];
#pragma unroll
    for (int mi = 0; mi < 4; mi++)
        aoffb[mi] = (uint32_t)((mi * 16 + (mat & 1) * 8 + swl) * 128);
    const uint32_t boffb = 8192u + (uint32_t)((w * 16 + (mat & 1) * 8 + swl) * 128);
    uint32_t cidx[4];
#pragma unroll
    for (int ks = 0; ks < 4; ks++)
        cidx[ks] = (uint32_t)(((ks * 2 + khf) ^ swl) << 4);

    float acc[3][4][2][4];
#pragma unroll
    for (int g = 0; g < 3; g++)
#pragma unroll
        for (int mi = 0; mi < 4; mi++)
#pragma unroll
            for (int nf = 0; nf < 2; nf++)
#pragma unroll
                for (int e = 0; e < 4; e++) acc[g][mi][nf][e] = 0.f;

#define ISSUE_TO(SB)                                                          \
    {                                                                         \
        _Pragma("unroll")                                                     \
        for (int j = 0; j < 4; j++) {                                         \
            cpa16((SB) + soA + j * 2048u, gA + (size_t)j * JSTRIDE);          \
            _Pragma("unroll")                                                 \
            for (int g = 0; g < 3; g++)                                       \
                cpa16((SB) + soA + 8192u + g * 8192u + j * 2048u,             \
                      gB[g] + (size_t)j * JSTRIDE);                           \
        }                                                                     \
    }
#define ADV()                                                                 \
    { gA += 128; gB[0] += 128; gB[1] += 128; gB[2] += 128; }

    // preload chunks 0,1 into slots 0,1
    ISSUE_TO(sbase); cpa_commit(); ADV();
    ISSUE_TO(sbase + STAGE); cpa_commit(); ADV();

    uint32_t rd = sbase;

    for (int i = 0; i < NK; i++) {
        cpa_wait1();
        __syncthreads();

#pragma unroll
        for (int ks = 0; ks < 4; ks++) {
            uint32_t a4[16], b4[12];
#pragma unroll
            for (int mi = 0; mi < 4; mi++)
                ldsm4(a4 + mi * 4, rd + aoffb[mi] + cidx[ks]);
            uint32_t bb = rd + boffb + cidx[ks];
            ldsm4(b4, bb);
            ldsm4(b4 + 4, bb + 8192u);
            ldsm4(b4 + 8, bb + 16384u);
#pragma unroll
            for (int g = 0; g < 3; g++)
#pragma unroll
                for (int mi = 0; mi < 4; mi++) {
                    mma16816(acc[g][mi][0], a4 + mi * 4, b4[g * 4 + 0], b4[g * 4 + 2]);
                    mma16816(acc[g][mi][1], a4 + mi * 4, b4[g * 4 + 1], b4[g * 4 + 3]);
                }
        }
        __syncthreads();

        if (i + 2 < NK) { ISSUE_TO(rd); ADV(); }
        cpa_commit();
        rd ^= STAGE;
    }

    // ---- epilogue ----
    float bA[2][2], bB[2][2], bC2[2][2], bD[2][2];
#pragma unroll
    for (int nf = 0; nf < 2; nf++) {
        int n = n0 + w * 16 + nf * 8 + (lane & 3) * 2;
        if (MODE == 0) {
            float2 i0 = *(const float2*)&e0[n],         h0 = *(const float2*)&e1[n];
            float2 i1 = *(const float2*)&e0[HID + n],   h1 = *(const float2*)&e1[HID + n];
            float2 i2 = *(const float2*)&e0[2*HID + n], h2 = *(const float2*)&e1[2*HID + n];
            bA[nf][0] = i0.x + h0.x; bA[nf][1] = i0.y + h0.y;
            bB[nf][0] = i1.x + h1.x; bB[nf][1] = i1.y + h1.y;
            bC2[nf][0] = i2.x;       bC2[nf][1] = i2.y;
            bD[nf][0] = h2.x;        bD[nf][1] = h2.y;
        } else {
            float2 v0 = *(const float2*)&e0[n];
            float2 v1 = *(const float2*)&e1[n];
            float2 v2 = *(const float2*)&e2[n];
            bA[nf][0] = v0.x; bA[nf][1] = v0.y;
            bB[nf][0] = v1.x; bB[nf][1] = v1.y;
            bC2[nf][0] = v2.x; bC2[nf][1] = v2.y;
        }
    }

#pragma unroll
    for (int mi = 0; mi < 4; mi++) {
#pragma unroll
        for (int half = 0; half < 2; half++) {
            const int m = m0 + mi * 16 + (lane >> 2) + half * 8;
#pragma unroll
            for (int nf = 0; nf < 2; nf++) {
                const int n = n0 + w * 16 + nf * 8 + (lane & 3) * 2;
                float res[2];
                float hv0 = 0.f, hv1 = 0.f;
                if (MODE == 1) {
                    uint32_t hw = *(const uint32_t*)(hin + (size_t)m * HID + n);
                    hv0 = h2f_lo(hw); hv1 = h2f_hi(hw);
                }
#pragma unroll
                for (int e = 0; e < 2; e++) {
                    float a0 = acc[0][mi][nf][half * 2 + e];
                    float a1 = acc[1][mi][nf][half * 2 + e];
                    float a2 = acc[2][mi][nf][half * 2 + e];
                    if (MODE == 0) {
                        float r = sigm_(a0 + bA[nf][e]);
                        float z = sigm_(a1 + bB[nf][e]);
                        float nn = tanh_(a2 + bC2[nf][e] + r * bD[nf][e]);
                        res[e] = (1.f - z) * nn;
                    } else {
                        float hh = tanh_(a0 + bA[nf][e]);
                        float t  = sigm_(a1 + bB[nf][e]);
                        float cc = sigm_(a2 + bC2[nf][e]);
                        float hi = (e == 0) ? hv0 : hv1;
                        res[e] = hh * t + hi * (1.f - cc);
                    }
                }
                if (WRH) {
                    *(uint32_t*)(outH + (size_t)m * HID + n) = f2h(res[0]) | (f2h(res[1]) << 16);
                } else {
                    *(float2*)(outF + (size_t)m * HID + n) = make_float2(res[0], res[1]);
                }
            }
        }
    }
}

extern "C" void kernel_launch(void* const* d_in, const int* in_sizes, int n_in,
                              void* d_out, int out_size)
{
    const float* x    = (const float*)d_in[0];
    const float* w_ih = (const float*)d_in[1];
    const float* b_ih = (const float*)d_in[3];
    const float* b_hh = (const float*)d_in[4];
    const float* WH   = (const float*)d_in[5];
    const float* bH   = (const float*)d_in[6];
    const float* WT   = (const float*)d_in[7];
    const float* bT   = (const float*)d_in[8];
    const float* WC   = (const float*)d_in[9];
    const float* bC   = (const float*)d_in[10];
    float* out = (float*)d_out;

    static bool attrSet = false;
    if (!attrSet) {
        cudaFuncSetAttribute(rhn_h<512, 0, 1>,  cudaFuncAttributeMaxDynamicSharedMemorySize, DSMEM_TOTAL);
        cudaFuncSetAttribute(rhn_h<1024, 1, 1>, cudaFuncAttributeMaxDynamicSharedMemorySize, DSMEM_TOTAL);
        cudaFuncSetAttribute(rhn_h<1024, 1, 0>, cudaFuncAttributeMaxDynamicSharedMemorySize, DSMEM_TOTAL);
        attrSet = true;
    }

    __half *x16, *w16, *WH16, *WT16, *WC16, *h16A, *h16B;
    cudaGetSymbolAddress((void**)&x16, g_x16);
    cudaGetSymbolAddress((void**)&w16, g_w16);
    cudaGetSymbolAddress((void**)&WH16, g_WH16);
    cudaGetSymbolAddress((void**)&WT16, g_WT16);
    cudaGetSymbolAddress((void**)&WC16, g_WC16);
    cudaGetSymbolAddress((void**)&h16A, g_h16A);
    cudaGetSymbolAddress((void**)&h16B, g_h16B);

    {
        int n4 = MROWS * 512 / 4;
        cvt4<<<(n4 + 255) / 256, 256>>>((const float4*)x, (uint2*)x16, n4);
        n4 = 3 * HID * 512 / 4;
        cvt4<<<(n4 + 255) / 256, 256>>>((const float4*)w_ih, (uint2*)w16, n4);
        n4 = 5 * HID * HID / 4;
        dim3 g((n4 + 255) / 256, 1, 3);
        cvt4w<<<g, 256>>>((const float4*)WH, (uint2*)WH16,
                          (const float4*)WT, (uint2*)WT16,
                          (const float4*)WC, (uint2*)WC16, n4);
    }

    dim3 grd(HID / 64, MROWS / 64);
    rhn_h<512, 0, 1><<<grd, 128, DSMEM_TOTAL>>>(
        x16,
        w16, w16 + (size_t)HID * 512, w16 + (size_t)2 * HID * 512,
        b_ih, b_hh, nullptr,
        nullptr, nullptr, h16A);

    for (int s = 0; s < 5; s++) {
        size_t wo = (size_t)s * HID * HID;
        const __half* ih = (s & 1) ? h16B : h16A;
        __half* oh = (s & 1) ? h16A : h16B;
        if (s == 4)
            rhn_h<1024, 1, 0><<<grd, 128, DSMEM_TOTAL>>>(
                ih, WH16 + wo, WT16 + wo, WC16 + wo,
                bH + s * HID, bT + s * HID, bC + s * HID,
                ih, out, nullptr);
        else
            rhn_h<1024, 1, 1><<<grd, 128, DSMEM_TOTAL>>>(
                ih, WH16 + wo, WT16 + wo, WC16 + wo,
                bH + s * HID, bT + s * HID, bC + s * HID,
                ih, nullptr, oh);
    }
}

// round 13
// speedup vs baseline: 3.4122x; 1.0011x over previous
#include <cuda_runtime.h>
#include <cuda_fp16.h>
#include <cstdint>

#define HID 1024
#define MROWS 32768
#define STAGE 32768
#define DSMEM_TOTAL (2 * STAGE)

// ---- static device scratch (allocation-free rule) ----
__device__ __align__(16) __half g_x16 [(size_t)MROWS * 512];
__device__ __align__(16) __half g_w16 [(size_t)3 * HID * 512];
__device__ __align__(16) __half g_WH16[(size_t)5 * HID * HID];
__device__ __align__(16) __half g_WT16[(size_t)5 * HID * HID];
__device__ __align__(16) __half g_WC16[(size_t)5 * HID * HID];
__device__ __align__(16) __half g_h16A[(size_t)MROWS * HID];
__device__ __align__(16) __half g_h16B[(size_t)MROWS * HID];

// ---- helpers ----
__device__ __forceinline__ uint32_t smem_u32(const void* p) {
    uint32_t a;
    asm("{ .reg .u64 t; cvta.to.shared.u64 t, %1; cvt.u32.u64 %0, t; }" : "=r"(a) : "l"(p));
    return a;
}
__device__ __forceinline__ void cpa16(uint32_t s, const void* g) {
    asm volatile("cp.async.cg.shared.global [%0], [%1], 16;" :: "r"(s), "l"(g));
}
__device__ __forceinline__ void cpa_commit() {
    asm volatile("cp.async.commit_group;" ::: "memory");
}
__device__ __forceinline__ void cpa_wait1() {
    asm volatile("cp.async.wait_group 1;" ::: "memory");
}
__device__ __forceinline__ void ldsm4(uint32_t* r, uint32_t a) {
    asm volatile("ldmatrix.sync.aligned.m8n8.x4.shared.b16 {%0,%1,%2,%3}, [%4];"
                 : "=r"(r[0]), "=r"(r[1]), "=r"(r[2]), "=r"(r[3]) : "r"(a));
}
__device__ __forceinline__ void mma16816(float* d, const uint32_t* a, uint32_t b0, uint32_t b1) {
    asm volatile(
        "mma.sync.aligned.m16n8k16.row.col.f32.f16.f16.f32 "
        "{%0,%1,%2,%3}, {%4,%5,%6,%7}, {%8,%9}, {%0,%1,%2,%3};"
        : "+f"(d[0]), "+f"(d[1]), "+f"(d[2]), "+f"(d[3])
        : "r"(a[0]), "r"(a[1]), "r"(a[2]), "r"(a[3]), "r"(b0), "r"(b1));
}
// swizzled byte offset inside a k64 (128B-row) fp16 tile: row r, 16B chunk c (0..7)
__device__ __forceinline__ uint32_t swz64(int r, int c) {
    return (uint32_t)(r * 128 + ((c ^ (r & 7)) << 4));
}
__device__ __forceinline__ float sigm_(float x) { return __fdividef(1.f, 1.f + __expf(-x)); }
__device__ __forceinline__ float tanh_(float x) {
    float ax = fabsf(x), e = __expf(-2.f * ax);
    float t = __fdividef(1.f - e, 1.f + e);
    return x >= 0.f ? t : -t;
}
__device__ __forceinline__ uint32_t f2h(float f) {
    return (uint32_t)__half_as_ushort(__float2half_rn(f));
}
__device__ __forceinline__ float h2f_lo(uint32_t u) {
    return __half2float(__ushort_as_half((unsigned short)(u & 0xFFFFu)));
}
__device__ __forceinline__ float h2f_hi(uint32_t u) {
    return __half2float(__ushort_as_half((unsigned short)(u >> 16)));
}

// ---- fp32 -> fp16 convert ----
__global__ void cvt4(const float4* __restrict__ src, uint2* __restrict__ dst, int n4) {
    int i = blockIdx.x * blockDim.x + threadIdx.x;
    if (i >= n4) return;
    float4 v = src[i];
    uint2 o;
    o.x = f2h(v.x) | (f2h(v.y) << 16);
    o.y = f2h(v.z) | (f2h(v.w) << 16);
    dst[i] = o;
}
__global__ void cvt4w(const float4* __restrict__ s0, uint2* __restrict__ d0,
                      const float4* __restrict__ s1, uint2* __restrict__ d1,
                      const float4* __restrict__ s2, uint2* __restrict__ d2, int n4) {
    int i = blockIdx.x * blockDim.x + threadIdx.x;
    if (i >= n4) return;
    const float4* src = blockIdx.z == 0 ? s0 : (blockIdx.z == 1 ? s1 : s2);
    uint2* dst = blockIdx.z == 0 ? d0 : (blockIdx.z == 1 ? d1 : d2);
    float4 v = src[i];
    uint2 o;
    o.x = f2h(v.x) | (f2h(v.y) << 16);
    o.y = f2h(v.z) | (f2h(v.w) << 16);
    dst[i] = o;
}

// ---- fused 3-gate fp16 mma.sync GEMM + epilogue ----
// CTA tile M=64, N=64 per gate, 3 gates. 128 threads, 4 warps (warp = 16-col n-group,
// covers all 64 M-rows). B LDSM redundancy 1, A redundancy 4. 3 CTAs/SM.
// k64 chunks, 2-stage double buffer. smem stage: A[0,8K); Bg at 8K+g*8K.
// A-fragments software-pipelined across the 4 k16 slices.
template<int KF, int MODE, int WRH>
__global__ void __launch_bounds__(128, 3)
rhn_h(const __half* __restrict__ Ah,
      const __half* __restrict__ B0, const __half* __restrict__ B1, const __half* __restrict__ B2,
      const float* __restrict__ e0, const float* __restrict__ e1, const float* __restrict__ e2,
      const __half* __restrict__ hin,
      float* __restrict__ outF, __half* __restrict__ outH)
{
    constexpr int NK = KF / 64;
    constexpr int JSTRIDE = 16 * KF * 2;   // 16 rows in bytes
    extern __shared__ __align__(128) uint8_t smemraw[];
    const uint32_t sbase = smem_u32(smemraw);

    const int tid = threadIdx.x;
    const int lane = tid & 31;
    const int w = tid >> 5;
    const int m0 = blockIdx.y * 64;
    const int n0 = blockIdx.x * 64;

    // ---- producer mapping: 16 x cpa16 per thread per stage ----
    const int br = tid >> 3;
    const int pc = tid & 7;
    const char* gA = (const char*)(Ah + (size_t)(m0 + br) * KF + pc * 8);
    const char* gB[3];
    {
        const __half* bp[3] = {B0, B1, B2};
#pragma unroll
        for (int g = 0; g < 3; g++)
            gB[g] = (const char*)(bp[g] + (size_t)(n0 + br) * KF + pc * 8);
    }
    const uint32_t soA = swz64(br, pc);

    // ---- consumer bases ----
    const int mat = lane >> 3;
    const int khf = lane >> 4;
    const int swl = lane & 7;
    uint32_t aoffb[4];
#pragma unroll
    for (int mi = 0; mi < 4; mi++)
        aoffb[mi] = (uint32_t)((mi * 16 + (mat & 1) * 8 + swl) * 128);
    const uint32_t boffb = 8192u + (uint32_t)((w * 16 + (mat & 1) * 8 + swl) * 128);
    uint32_t cidx[4];
#pragma unroll
    for (int ks = 0; ks < 4; ks++)
        cidx[ks] = (uint32_t)(((ks * 2 + khf) ^ swl) << 4);

    float acc[3][4][2][4];
#pragma unroll
    for (int g = 0; g < 3; g++)
#pragma unroll
        for (int mi = 0; mi < 4; mi++)
#pragma unroll
            for (int nf = 0; nf < 2; nf++)
#pragma unroll
                for (int e = 0; e < 4; e++) acc[g][mi][nf][e] = 0.f;

#define ISSUE_TO(SB)                                                          \
    {                                                                         \
        _Pragma("unroll")                                                     \
        for (int j = 0; j < 4; j++) {                                         \
            cpa16((SB) + soA + j * 2048u, gA + (size_t)j * JSTRIDE);          \
            _Pragma("unroll")                                                 \
            for (int g = 0; g < 3; g++)                                       \
                cpa16((SB) + soA + 8192u + g * 8192u + j * 2048u,             \
                      gB[g] + (size_t)j * JSTRIDE);                           \
        }                                                                     \
    }
#define ADV()                                                                 \
    { gA += 128; gB[0] += 128; gB[1] += 128; gB[2] += 128; }

#define LDA(DST, KS)                                                          \
    {                                                                         \
        _Pragma("unroll")                                                     \
        for (int mi = 0; mi < 4; mi++)                                        \
            ldsm4((DST) + mi * 4, rd + aoffb[mi] + cidx[KS]);                 \
    }
#define LDB(DST, KS)                                                          \
    {                                                                         \
        uint32_t bb_ = rd + boffb + cidx[KS];                                 \
        ldsm4((DST), bb_);                                                    \
        ldsm4((DST) + 4, bb_ + 8192u);                                        \
        ldsm4((DST) + 8, bb_ + 16384u);                                       \
    }
#define MMAALL(A4, B4)                                                        \
    {                                                                         \
        _Pragma("unroll")                                                     \
        for (int g = 0; g < 3; g++)                                           \
            _Pragma("unroll")                                                 \
            for (int mi = 0; mi < 4; mi++) {                                  \
                mma16816(acc[g][mi][0], (A4) + mi * 4, (B4)[g * 4 + 0], (B4)[g * 4 + 2]); \
                mma16816(acc[g][mi][1], (A4) + mi * 4, (B4)[g * 4 + 1], (B4)[g * 4 + 3]); \
            }                                                                 \
    }

    // preload chunks 0,1 into slots 0,1
    ISSUE_TO(sbase); cpa_commit(); ADV();
    ISSUE_TO(sbase + STAGE); cpa_commit(); ADV();

    uint32_t rd = sbase;

    for (int i = 0; i < NK; i++) {
        cpa_wait1();
        __syncthreads();

        {
            uint32_t aX[16], aY[16], b4[12];
            // software-pipelined A fragments across the 4 k16 slices
            LDA(aX, 0);
            LDB(b4, 0); LDA(aY, 1); MMAALL(aX, b4);
            LDB(b4, 1); LDA(aX, 2); MMAALL(aY, b4);
            LDB(b4, 2); LDA(aY, 3); MMAALL(aX, b4);
            LDB(b4, 3);             MMAALL(aY, b4);
        }
        __syncthreads();

        if (i + 2 < NK) { ISSUE_TO(rd); ADV(); }
        cpa_commit();
        rd ^= STAGE;
    }

    // ---- epilogue ----
    float bA[2][2], bB[2][2], bC2[2][2], bD[2][2];
#pragma unroll
    for (int nf = 0; nf < 2; nf++) {
        int n = n0 + w * 16 + nf * 8 + (lane & 3) * 2;
        if (MODE == 0) {
            float2 i0 = *(const float2*)&e0[n],         h0 = *(const float2*)&e1[n];
            float2 i1 = *(const float2*)&e0[HID + n],   h1 = *(const float2*)&e1[HID + n];
            float2 i2 = *(const float2*)&e0[2*HID + n], h2 = *(const float2*)&e1[2*HID + n];
            bA[nf][0] = i0.x + h0.x; bA[nf][1] = i0.y + h0.y;
            bB[nf][0] = i1.x + h1.x; bB[nf][1] = i1.y + h1.y;
            bC2[nf][0] = i2.x;       bC2[nf][1] = i2.y;
            bD[nf][0] = h2.x;        bD[nf][1] = h2.y;
        } else {
            float2 v0 = *(const float2*)&e0[n];
            float2 v1 = *(const float2*)&e1[n];
            float2 v2 = *(const float2*)&e2[n];
            bA[nf][0] = v0.x; bA[nf][1] = v0.y;
            bB[nf][0] = v1.x; bB[nf][1] = v1.y;
            bC2[nf][0] = v2.x; bC2[nf][1] = v2.y;
        }
    }

#pragma unroll
    for (int mi = 0; mi < 4; mi++) {
#pragma unroll
        for (int half = 0; half < 2; half++) {
            const int m = m0 + mi * 16 + (lane >> 2) + half * 8;
#pragma unroll
            for (int nf = 0; nf < 2; nf++) {
                const int n = n0 + w * 16 + nf * 8 + (lane & 3) * 2;
                float res[2];
                float hv0 = 0.f, hv1 = 0.f;
                if (MODE == 1) {
                    uint32_t hw = *(const uint32_t*)(hin + (size_t)m * HID + n);
                    hv0 = h2f_lo(hw); hv1 = h2f_hi(hw);
                }
#pragma unroll
                for (int e = 0; e < 2; e++) {
                    float a0 = acc[0][mi][nf][half * 2 + e];
                    float a1 = acc[1][mi][nf][half * 2 + e];
                    float a2 = acc[2][mi][nf][half * 2 + e];
                    if (MODE == 0) {
                        float r = sigm_(a0 + bA[nf][e]);
                        float z = sigm_(a1 + bB[nf][e]);
                        float nn = tanh_(a2 + bC2[nf][e] + r * bD[nf][e]);
                        res[e] = (1.f - z) * nn;
                    } else {
                        float hh = tanh_(a0 + bA[nf][e]);
                        float t  = sigm_(a1 + bB[nf][e]);
                        float cc = sigm_(a2 + bC2[nf][e]);
                        float hi = (e == 0) ? hv0 : hv1;
                        res[e] = hh * t + hi * (1.f - cc);
                    }
                }
                if (WRH) {
                    *(uint32_t*)(outH + (size_t)m * HID + n) = f2h(res[0]) | (f2h(res[1]) << 16);
                } else {
                    *(float2*)(outF + (size_t)m * HID + n) = make_float2(res[0], res[1]);
                }
            }
        }
    }
}

extern "C" void kernel_launch(void* const* d_in, const int* in_sizes, int n_in,
                              void* d_out, int out_size)
{
    const float* x    = (const float*)d_in[0];
    const float* w_ih = (const float*)d_in[1];
    const float* b_ih = (const float*)d_in[3];
    const float* b_hh = (const float*)d_in[4];
    const float* WH   = (const float*)d_in[5];
    const float* bH   = (const float*)d_in[6];
    const float* WT   = (const float*)d_in[7];
    const float* bT   = (const float*)d_in[8];
    const float* WC   = (const float*)d_in[9];
    const float* bC   = (const float*)d_in[10];
    float* out = (float*)d_out;

    static bool attrSet = false;
    if (!attrSet) {
        cudaFuncSetAttribute(rhn_h<512, 0, 1>,  cudaFuncAttributeMaxDynamicSharedMemorySize, DSMEM_TOTAL);
        cudaFuncSetAttribute(rhn_h<1024, 1, 1>, cudaFuncAttributeMaxDynamicSharedMemorySize, DSMEM_TOTAL);
        cudaFuncSetAttribute(rhn_h<1024, 1, 0>, cudaFuncAttributeMaxDynamicSharedMemorySize, DSMEM_TOTAL);
        attrSet = true;
    }

    __half *x16, *w16, *WH16, *WT16, *WC16, *h16A, *h16B;
    cudaGetSymbolAddress((void**)&x16, g_x16);
    cudaGetSymbolAddress((void**)&w16, g_w16);
    cudaGetSymbolAddress((void**)&WH16, g_WH16);
    cudaGetSymbolAddress((void**)&WT16, g_WT16);
    cudaGetSymbolAddress((void**)&WC16, g_WC16);
    cudaGetSymbolAddress((void**)&h16A, g_h16A);
    cudaGetSymbolAddress((void**)&h16B, g_h16B);

    {
        int n4 = MROWS * 512 / 4;
        cvt4<<<(n4 + 255) / 256, 256>>>((const float4*)x, (uint2*)x16, n4);
        n4 = 3 * HID * 512 / 4;
        cvt4<<<(n4 + 255) / 256, 256>>>((const float4*)w_ih, (uint2*)w16, n4);
        n4 = 5 * HID * HID / 4;
        dim3 g((n4 + 255) / 256, 1, 3);
        cvt4w<<<g, 256>>>((const float4*)WH, (uint2*)WH16,
                          (const float4*)WT, (uint2*)WT16,
                          (const float4*)WC, (uint2*)WC16, n4);
    }

    dim3 grd(HID / 64, MROWS / 64);
    rhn_h<512, 0, 1><<<grd, 128, DSMEM_TOTAL>>>(
        x16,
        w16, w16 + (size_t)HID * 512, w16 + (size_t)2 * HID * 512,
        b_ih, b_hh, nullptr,
        nullptr, nullptr, h16A);

    for (int s = 0; s < 5; s++) {
        size_t wo = (size_t)s * HID * HID;
        const __half* ih = (s & 1) ? h16B : h16A;
        __half* oh = (s & 1) ? h16A : h16B;
        if (s == 4)
            rhn_h<1024, 1, 0><<<grd, 128, DSMEM_TOTAL>>>(
                ih, WH16 + wo, WT16 + wo, WC16 + wo,
                bH + s * HID, bT + s * HID, bC + s * HID,
                ih, out, nullptr);
        else
            rhn_h<1024, 1, 1><<<grd, 128, DSMEM_TOTAL>>>(
                ih, WH16 + wo, WT16 + wo, WC16 + wo,
                bH + s * HID, bT + s * HID, bC + s * HID,
                ih, nullptr, oh);
    }
}